// round 1
// baseline (speedup 1.0000x reference)
#include <cuda_runtime.h>
#include <cstdint>

#define T_TOK 4096
#define SD    1024
#define ED    512
#define DD    20
#define HID   1024
#define GI    2580
#define NSPAN 40915
#define MAXW  10

// ---------------- scratch (static device globals; no allocations) ----------------
__device__ float g_A1[(size_t)T_TOK * HID];
__device__ float g_A2[(size_t)T_TOK * HID];
__device__ float g_attns[T_TOK];
__device__ float g_P1[(size_t)T_TOK * HID];
__device__ float g_P2[(size_t)T_TOK * HID];
__device__ float g_E1[(size_t)T_TOK * HID];
__device__ float g_WB9[9 * HID];
__device__ float g_h1[(size_t)NSPAN * HID];
__device__ float g_h2[(size_t)NSPAN * HID];

// ---------------- generic SGEMM: C[M,1024] = A[M,K] @ B[K,1024] (+bias)(+relu) ----
// 128x128 block tile, BK=8, 256 threads, 8x8 per-thread micro-tile, double-buffered.
__global__ __launch_bounds__(256, 2) void sgemm_n1024(
    const float* __restrict__ A, const float* __restrict__ B,
    const float* __restrict__ bias, float* __restrict__ C,
    int M, int K, int relu)
{
    __shared__ float As[2][8][128];
    __shared__ float Bs[2][8][128];

    const int tid = threadIdx.x;
    const int bm = blockIdx.x * 128;
    const int bn = blockIdx.y * 128;

    const int arow = tid >> 1;          // 0..127
    const int acol = (tid & 1) * 4;     // 0 or 4
    const int brow = tid >> 5;          // 0..7
    const int bcol = (tid & 31) * 4;    // 0..124

    const int tx = tid & 15, ty = tid >> 4;
    const int m0 = ty * 8, n0 = tx * 8;

    float acc[8][8];
#pragma unroll
    for (int i = 0; i < 8; i++)
#pragma unroll
        for (int j = 0; j < 8; j++) acc[i][j] = 0.f;

    const int nt = K >> 3;
    const bool arow_ok = (bm + arow) < M;
    const float* Aptr = A + (size_t)(bm + arow) * K + acol;
    const float* Bptr = B + (size_t)brow * 1024 + bn + bcol;

    float4 av, bv;
    av = arow_ok ? *(const float4*)Aptr : make_float4(0.f, 0.f, 0.f, 0.f);
    bv = *(const float4*)Bptr;
    As[0][acol + 0][arow] = av.x; As[0][acol + 1][arow] = av.y;
    As[0][acol + 2][arow] = av.z; As[0][acol + 3][arow] = av.w;
    *(float4*)&Bs[0][brow][bcol] = bv;
    __syncthreads();

    int buf = 0;
    for (int t = 0; t < nt; ++t) {
        if (t + 1 < nt) {
            av = arow_ok ? *(const float4*)(Aptr + (size_t)(t + 1) * 8)
                         : make_float4(0.f, 0.f, 0.f, 0.f);
            bv = *(const float4*)(Bptr + (size_t)(t + 1) * 8 * 1024);
        }
#pragma unroll
        for (int kk = 0; kk < 8; ++kk) {
            float4 a0 = *(const float4*)&As[buf][kk][m0];
            float4 a1 = *(const float4*)&As[buf][kk][m0 + 4];
            float4 b0 = *(const float4*)&Bs[buf][kk][n0];
            float4 b1 = *(const float4*)&Bs[buf][kk][n0 + 4];
            float ar[8] = {a0.x, a0.y, a0.z, a0.w, a1.x, a1.y, a1.z, a1.w};
            float br[8] = {b0.x, b0.y, b0.z, b0.w, b1.x, b1.y, b1.z, b1.w};
#pragma unroll
            for (int i = 0; i < 8; i++)
#pragma unroll
                for (int j = 0; j < 8; j++)
                    acc[i][j] = fmaf(ar[i], br[j], acc[i][j]);
        }
        if (t + 1 < nt) {
            int nb = buf ^ 1;
            As[nb][acol + 0][arow] = av.x; As[nb][acol + 1][arow] = av.y;
            As[nb][acol + 2][arow] = av.z; As[nb][acol + 3][arow] = av.w;
            *(float4*)&Bs[nb][brow][bcol] = bv;
        }
        __syncthreads();
        buf ^= 1;
    }

    float bb[8];
    if (bias) {
        float4 c0 = *(const float4*)(bias + bn + n0);
        float4 c1 = *(const float4*)(bias + bn + n0 + 4);
        bb[0] = c0.x; bb[1] = c0.y; bb[2] = c0.z; bb[3] = c0.w;
        bb[4] = c1.x; bb[5] = c1.y; bb[6] = c1.z; bb[7] = c1.w;
    } else {
#pragma unroll
        for (int j = 0; j < 8; j++) bb[j] = 0.f;
    }

#pragma unroll
    for (int i = 0; i < 8; i++) {
        int row = bm + m0 + i;
        if (row < M) {
            float v[8];
#pragma unroll
            for (int j = 0; j < 8; j++) {
                float x = acc[i][j] + bb[j];
                v[j] = relu ? fmaxf(x, 0.f) : x;
            }
            float4* cp = (float4*)(C + (size_t)row * 1024 + bn + n0);
            cp[0] = make_float4(v[0], v[1], v[2], v[3]);
            cp[1] = make_float4(v[4], v[5], v[6], v[7]);
        }
    }
}

// ---------------- GEMV: out[i] = A[i,:1024] . W + b[0] ----------------
__global__ void gemv1024(const float* __restrict__ A, const float* __restrict__ W,
                         const float* __restrict__ b, float* __restrict__ out, int M)
{
    int warp = (blockIdx.x * blockDim.x + threadIdx.x) >> 5;
    int lane = threadIdx.x & 31;
    if (warp >= M) return;
    const float4* a = (const float4*)(A + (size_t)warp * 1024);
    const float4* w4 = (const float4*)W;
    float acc = 0.f;
#pragma unroll
    for (int i = 0; i < 8; i++) {
        int idx = lane + i * 32;
        float4 x = a[idx], y = w4[idx];
        acc += x.x * y.x + x.y * y.y + x.z * y.z + x.w * y.w;
    }
#pragma unroll
    for (int o = 16; o; o >>= 1) acc += __shfl_xor_sync(0xffffffffu, acc, o);
    if (lane == 0) out[warp] = acc + b[0];
}

// ---------------- WB9[b] = width_embed[b] @ W1d + score_b1  (9 x 1024) ----------
__global__ void wb9_kernel(const float* __restrict__ width_embed,
                           const float* __restrict__ W1, const float* __restrict__ b1)
{
    int bkt = blockIdx.x;          // 0..8
    int j4 = threadIdx.x;          // 0..255 -> float4 over 1024 cols
    float4 acc = ((const float4*)b1)[j4];
#pragma unroll
    for (int k = 0; k < DD; k++) {
        float wv = width_embed[bkt * DD + k];
        float4 ww = ((const float4*)(W1 + (size_t)(2 * SD + ED + k) * HID))[j4];
        acc.x = fmaf(wv, ww.x, acc.x); acc.y = fmaf(wv, ww.y, acc.y);
        acc.z = fmaf(wv, ww.z, acc.z); acc.w = fmaf(wv, ww.w, acc.w);
    }
    ((float4*)(g_WB9 + (size_t)bkt * HID))[j4] = acc;
}

// ---------------- span kernel: writes g_i row + h1 row per span ----------------
__global__ void span_kernel(const float* __restrict__ states,
                            const float* __restrict__ embeds,
                            const float* __restrict__ width_embed,
                            const int* __restrict__ starts,
                            const int* __restrict__ widths,
                            float* __restrict__ gi, float* __restrict__ h1)
{
    const int n = blockIdx.x;
    const int s = starts[n];
    const int w = widths[n];
    const int e = s + w - 1;
    const int bucket = (w >= 1) + (w >= 2) + (w >= 3) + (w >= 4) +
                       (w >= 8) + (w >= 16) + (w >= 32) + (w >= 64);

    // softmax weights over valid slots (computed redundantly per thread; broadcast loads)
    float wt[MAXW];
    float mx = -3.4e38f;
#pragma unroll
    for (int i = 0; i < MAXW; i++) {
        int p = s + i; if (p > T_TOK - 1) p = T_TOK - 1;
        float a = (i < w) ? g_attns[p] : -1e30f;
        wt[i] = a;
        mx = fmaxf(mx, a);
    }
    float sum = 0.f;
#pragma unroll
    for (int i = 0; i < MAXW; i++) {
        float v = (i < w) ? expf(wt[i] - mx) : 0.f;
        wt[i] = v; sum += v;
    }
    const float inv = 1.f / sum;

    const int tid = threadIdx.x;   // 256 threads
    float* girow = gi + (size_t)n * GI;

    // segment 1+2: states[s], states[e]  (1024 each)
    ((float4*)girow)[tid] = ((const float4*)(states + (size_t)s * SD))[tid];
    ((float4*)(girow + SD))[tid] = ((const float4*)(states + (size_t)e * SD))[tid];

    // segment 3: attention-pooled embeds (512) ; segment 4: width embed (20)
    if (tid < 128) {
        float4 acc = make_float4(0.f, 0.f, 0.f, 0.f);
#pragma unroll
        for (int i = 0; i < MAXW; i++) {
            if (i < w) {
                float4 v = ((const float4*)(embeds + (size_t)(s + i) * ED))[tid];
                float ww = wt[i] * inv;
                acc.x = fmaf(ww, v.x, acc.x); acc.y = fmaf(ww, v.y, acc.y);
                acc.z = fmaf(ww, v.z, acc.z); acc.w = fmaf(ww, v.w, acc.w);
            }
        }
        ((float4*)(girow + 2 * SD))[tid] = acc;
    } else if (tid < 128 + DD) {
        int j = tid - 128;
        girow[2 * SD + ED + j] = width_embed[bucket * DD + j];
    }

    // h1[n] = relu(P1[s] + P2[e] + sum_w wt*E1[s+w] + WB9[bucket](incl. b1))
    {
        float4 a = ((const float4*)(g_P1 + (size_t)s * HID))[tid];
        float4 b = ((const float4*)(g_P2 + (size_t)e * HID))[tid];
        float4 c = ((const float4*)(g_WB9 + (size_t)bucket * HID))[tid];
        float4 acc = make_float4(a.x + b.x + c.x, a.y + b.y + c.y,
                                 a.z + b.z + c.z, a.w + b.w + c.w);
#pragma unroll
        for (int i = 0; i < MAXW; i++) {
            if (i < w) {
                float4 v = ((const float4*)(g_E1 + (size_t)(s + i) * HID))[tid];
                float ww = wt[i] * inv;
                acc.x = fmaf(ww, v.x, acc.x); acc.y = fmaf(ww, v.y, acc.y);
                acc.z = fmaf(ww, v.z, acc.z); acc.w = fmaf(ww, v.w, acc.w);
            }
        }
        acc.x = fmaxf(acc.x, 0.f); acc.y = fmaxf(acc.y, 0.f);
        acc.z = fmaxf(acc.z, 0.f); acc.w = fmaxf(acc.w, 0.f);
        ((float4*)(h1 + (size_t)n * HID))[tid] = acc;
    }
}

// ---------------- launcher ----------------
extern "C" void kernel_launch(void* const* d_in, const int* in_sizes, int n_in,
                              void* d_out, int out_size)
{
    const float* states = (const float*)d_in[0];
    const float* embeds = (const float*)d_in[1];
    const float* aW1 = (const float*)d_in[2];
    const float* ab1 = (const float*)d_in[3];
    const float* aW2 = (const float*)d_in[4];
    const float* ab2 = (const float*)d_in[5];
    const float* aW3 = (const float*)d_in[6];
    const float* ab3 = (const float*)d_in[7];
    const float* sW1 = (const float*)d_in[8];
    const float* sb1 = (const float*)d_in[9];
    const float* sW2 = (const float*)d_in[10];
    const float* sb2 = (const float*)d_in[11];
    const float* sW3 = (const float*)d_in[12];
    const float* sb3 = (const float*)d_in[13];
    const float* wemb = (const float*)d_in[14];
    const int* starts = (const int*)d_in[15];
    const int* widths = (const int*)d_in[16];

    float* out = (float*)d_out;
    float* gi = out;
    float* scores = out + (size_t)NSPAN * GI;

    float *A1, *A2, *attns, *P1, *P2, *E1, *h1, *h2;
    cudaGetSymbolAddress((void**)&A1, g_A1);
    cudaGetSymbolAddress((void**)&A2, g_A2);
    cudaGetSymbolAddress((void**)&attns, g_attns);
    cudaGetSymbolAddress((void**)&P1, g_P1);
    cudaGetSymbolAddress((void**)&P2, g_P2);
    cudaGetSymbolAddress((void**)&E1, g_E1);
    cudaGetSymbolAddress((void**)&h1, g_h1);
    cudaGetSymbolAddress((void**)&h2, g_h2);

    dim3 gT((T_TOK + 127) / 128, 8);

    // token attention MLP
    sgemm_n1024<<<gT, 256>>>(states, aW1, ab1, A1, T_TOK, SD, 1);
    sgemm_n1024<<<gT, 256>>>(A1, aW2, ab2, A2, T_TOK, HID, 1);
    gemv1024<<<(T_TOK * 32 + 255) / 256, 256>>>(A2, aW3, ab3, attns, T_TOK);

    // score layer-1 decomposition precompute (token-level)
    sgemm_n1024<<<gT, 256>>>(states, sW1, nullptr, P1, T_TOK, SD, 0);
    sgemm_n1024<<<gT, 256>>>(states, sW1 + (size_t)SD * HID, nullptr, P2, T_TOK, SD, 0);
    sgemm_n1024<<<gT, 256>>>(embeds, sW1 + (size_t)2 * SD * HID, nullptr, E1, T_TOK, ED, 0);
    wb9_kernel<<<9, 256>>>(wemb, sW1, sb1);

    // per-span: g_i output + fused layer-1 (h1)
    span_kernel<<<NSPAN, 256>>>(states, embeds, wemb, starts, widths, gi, h1);

    // score layer-2 + layer-3
    dim3 gN((NSPAN + 127) / 128, 8);
    sgemm_n1024<<<gN, 256>>>(h1, sW2, sb2, h2, NSPAN, HID, 1);
    gemv1024<<<((NSPAN * 32) + 255) / 256, 256>>>(h2, sW3, sb3, scores, NSPAN);
}

// round 6
// speedup vs baseline: 1.3636x; 1.3636x over previous
#include <cuda_runtime.h>
#include <cuda_fp16.h>
#include <cstdint>

#define T_TOK 4096
#define SD    1024
#define ED    512
#define DD    20
#define HID   1024
#define GI    2580
#define NSPAN 40915
#define MAXW  10

// ---------------- scratch (static device globals; no allocations) ----------------
__device__ float g_A1[(size_t)T_TOK * HID];
__device__ float g_A2[(size_t)T_TOK * HID];
__device__ float g_attns[T_TOK];
__device__ float g_P1[(size_t)T_TOK * HID];
__device__ float g_P2[(size_t)T_TOK * HID];
__device__ float g_E1[(size_t)T_TOK * HID];
__device__ float g_WB9[9 * HID];
__device__ float g_h1[(size_t)NSPAN * HID];
__device__ float g_h2[(size_t)NSPAN * HID];
// transposed weights [N=1024 rows, K cols]
__device__ float g_WTa1[(size_t)HID * SD];
__device__ float g_WTa2[(size_t)HID * HID];
__device__ float g_WTp1[(size_t)HID * SD];
__device__ float g_WTp2[(size_t)HID * SD];
__device__ float g_WTe1[(size_t)HID * ED];
__device__ float g_WTs2[(size_t)HID * HID];

// ======================= helpers =======================
__device__ __forceinline__ uint32_t smem_u32(const void* p) {
    uint32_t a;
    asm("{ .reg .u64 t; cvta.to.shared.u64 t, %1; cvt.u32.u64 %0, t; }" : "=r"(a) : "l"(p));
    return a;
}

__device__ __forceinline__ void ldmx4(uint32_t* r, uint32_t addr) {
    asm volatile("ldmatrix.sync.aligned.m8n8.x4.shared.b16 {%0,%1,%2,%3}, [%4];"
                 : "=r"(r[0]), "=r"(r[1]), "=r"(r[2]), "=r"(r[3]) : "r"(addr));
}

__device__ __forceinline__ void mma16816(float* c, const uint32_t* a, const uint32_t* b) {
    asm volatile(
        "mma.sync.aligned.m16n8k16.row.col.f32.f16.f16.f32 "
        "{%0,%1,%2,%3}, {%4,%5,%6,%7}, {%8,%9}, {%0,%1,%2,%3};"
        : "+f"(c[0]), "+f"(c[1]), "+f"(c[2]), "+f"(c[3])
        : "r"(a[0]), "r"(a[1]), "r"(a[2]), "r"(a[3]), "r"(b[0]), "r"(b[1]));
}

__device__ __forceinline__ uint32_t h2u(half2 h) {
    return *reinterpret_cast<uint32_t*>(&h);
}

// split float4 into fp16 hi/lo (Dekker); returns packed uint2 for hi and lo (4 halfs each)
__device__ __forceinline__ void split4(float4 v, uint2& hi, uint2& lo) {
    half2 h01 = __floats2half2_rn(v.x, v.y);
    half2 h23 = __floats2half2_rn(v.z, v.w);
    float2 f01 = __half22float2(h01);
    float2 f23 = __half22float2(h23);
    half2 l01 = __floats2half2_rn(v.x - f01.x, v.y - f01.y);
    half2 l23 = __floats2half2_rn(v.z - f23.x, v.w - f23.y);
    hi.x = h2u(h01); hi.y = h2u(h23);
    lo.x = h2u(l01); lo.y = h2u(l23);
}

// ======================= fp16x3 mma.sync GEMM ==============================
// C[M,1024] = A[M,K] @ BT^T   (BT is [1024,K] row-major), +bias, optional relu.
// CTA 128x128, KC=32, 8 warps (2x4), warp tile 64x32, double-buffered smem.
// fp32-equivalent accuracy via hi/lo fp16 split: hh + hl + lh.
#define TM 128
#define TN 128
#define KC 32
#define RS 80                      // smem row stride bytes (64B data + 16B pad)
#define TILE_B (128 * RS)          // 10240
#define STAGE_B (4 * TILE_B)       // A_hi A_lo B_hi B_lo = 40960
#define GEMM_SMEM (2 * STAGE_B)    // 81920

__global__ __launch_bounds__(256, 1) void hgemm_x3(
    const float* __restrict__ A, const float* __restrict__ BT,
    const float* __restrict__ bias, float* __restrict__ C,
    int M, int K, int relu)
{
    extern __shared__ char smem[];
    const uint32_t sbase = smem_u32(smem);

    const int tid = threadIdx.x;
    const int lane = tid & 31;
    const int wid = tid >> 5;
    const int wm = (wid >> 2) * 64;      // warp M offset (0 or 64)
    const int wn = (wid & 3) * 32;       // warp N offset (0..96)
    const int bn = blockIdx.x * TN;      // N-fastest for A-tile L2 reuse
    const int bm = blockIdx.y * TM;

    // per-thread load plan: 4 float4 slots each for A and B
    // idx = tid + 256*i : row = idx>>3 (0..127), c4 = idx&7 (float4 within 32 floats)
    uint32_t st_off[4];
    const float* a_gp[4]; bool a_ok[4];
    const float* b_gp[4];
#pragma unroll
    for (int i = 0; i < 4; i++) {
        int idx = tid + 256 * i;
        int row = idx >> 3, c4 = idx & 7;
        st_off[i] = (uint32_t)(row * RS + c4 * 8);
        a_ok[i] = (bm + row) < M;
        a_gp[i] = A + (size_t)(bm + row) * K + c4 * 4;
        b_gp[i] = BT + (size_t)(bn + row) * K + c4 * 4;
    }

    float acc[4][4][4];
#pragma unroll
    for (int mi = 0; mi < 4; mi++)
#pragma unroll
        for (int ni = 0; ni < 4; ni++)
#pragma unroll
            for (int q = 0; q < 4; q++) acc[mi][ni][q] = 0.f;

    const int nchunks = K / KC;
    float4 av[4], bv[4];

    // prime stage 0
#pragma unroll
    for (int i = 0; i < 4; i++) {
        av[i] = a_ok[i] ? *(const float4*)(a_gp[i]) : make_float4(0.f, 0.f, 0.f, 0.f);
        bv[i] = *(const float4*)(b_gp[i]);
    }
    {
        char* s = smem;
#pragma unroll
        for (int i = 0; i < 4; i++) {
            uint2 hi, lo;
            split4(av[i], hi, lo);
            *(uint2*)(s + st_off[i]) = hi;
            *(uint2*)(s + TILE_B + st_off[i]) = lo;
            split4(bv[i], hi, lo);
            *(uint2*)(s + 2 * TILE_B + st_off[i]) = hi;
            *(uint2*)(s + 3 * TILE_B + st_off[i]) = lo;
        }
    }
    __syncthreads();

    const int lr = lane & 15;
    const int ch = (lane >> 4) * 16;     // k-half byte offset for ldmatrix

    for (int c = 0; c < nchunks; ++c) {
        // prefetch next chunk (global -> regs)
        if (c + 1 < nchunks) {
            int kc = (c + 1) * KC;
#pragma unroll
            for (int i = 0; i < 4; i++) {
                av[i] = a_ok[i] ? *(const float4*)(a_gp[i] + kc) : make_float4(0.f, 0.f, 0.f, 0.f);
                bv[i] = *(const float4*)(b_gp[i] + kc);
            }
        }

        // compute from stage (c&1)
        const uint32_t sb = sbase + (uint32_t)(c & 1) * STAGE_B;
#pragma unroll
        for (int ks = 0; ks < 2; ks++) {
            const uint32_t colb = (uint32_t)(ks * 32 + ch);
            uint32_t aH[4][4], aL[4][4], bH[4][2], bL[4][2];
#pragma unroll
            for (int mi = 0; mi < 4; mi++) {
                uint32_t rowo = (uint32_t)((wm + mi * 16 + lr) * RS) + colb;
                ldmx4(aH[mi], sb + rowo);
                ldmx4(aL[mi], sb + TILE_B + rowo);
            }
#pragma unroll
            for (int g = 0; g < 2; g++) {
                uint32_t rowo = (uint32_t)((wn + g * 16 + lr) * RS) + colb;
                uint32_t r[4];
                ldmx4(r, sb + 2 * TILE_B + rowo);
                bH[g * 2][0] = r[0]; bH[g * 2][1] = r[2];
                bH[g * 2 + 1][0] = r[1]; bH[g * 2 + 1][1] = r[3];
                ldmx4(r, sb + 3 * TILE_B + rowo);
                bL[g * 2][0] = r[0]; bL[g * 2][1] = r[2];
                bL[g * 2 + 1][0] = r[1]; bL[g * 2 + 1][1] = r[3];
            }
#pragma unroll
            for (int mi = 0; mi < 4; mi++)
#pragma unroll
                for (int ni = 0; ni < 4; ni++) {
                    mma16816(acc[mi][ni], aH[mi], bH[ni]);
                    mma16816(acc[mi][ni], aH[mi], bL[ni]);
                    mma16816(acc[mi][ni], aL[mi], bH[ni]);
                }
        }

        // store next chunk into the other stage
        if (c + 1 < nchunks) {
            char* s = smem + ((c + 1) & 1) * STAGE_B;
#pragma unroll
            for (int i = 0; i < 4; i++) {
                uint2 hi, lo;
                split4(av[i], hi, lo);
                *(uint2*)(s + st_off[i]) = hi;
                *(uint2*)(s + TILE_B + st_off[i]) = lo;
                split4(bv[i], hi, lo);
                *(uint2*)(s + 2 * TILE_B + st_off[i]) = hi;
                *(uint2*)(s + 3 * TILE_B + st_off[i]) = lo;
            }
        }
        __syncthreads();
    }

    // epilogue
    const int mrow = lane >> 2;
    const int ncol = (lane & 3) * 2;
#pragma unroll
    for (int mi = 0; mi < 4; mi++) {
#pragma unroll
        for (int ni = 0; ni < 4; ni++) {
            int n0 = bn + wn + ni * 8 + ncol;
            float b0 = bias ? bias[n0] : 0.f;
            float b1 = bias ? bias[n0 + 1] : 0.f;
            int m0 = bm + wm + mi * 16 + mrow;
            if (m0 < M) {
                float2 v;
                v.x = acc[mi][ni][0] + b0;
                v.y = acc[mi][ni][1] + b1;
                if (relu) { v.x = fmaxf(v.x, 0.f); v.y = fmaxf(v.y, 0.f); }
                *(float2*)(C + (size_t)m0 * 1024 + n0) = v;
            }
            int m1 = m0 + 8;
            if (m1 < M) {
                float2 v;
                v.x = acc[mi][ni][2] + b0;
                v.y = acc[mi][ni][3] + b1;
                if (relu) { v.x = fmaxf(v.x, 0.f); v.y = fmaxf(v.y, 0.f); }
                *(float2*)(C + (size_t)m1 * 1024 + n0) = v;
            }
        }
    }
}

// ---------------- weight transpose: WT[n*K+k] = W[k*1024+n] ----------------
__global__ void transpose_kn(const float* __restrict__ W, float* __restrict__ WT, int K)
{
    __shared__ float tile[32][33];
    int kx = blockIdx.x * 32, ny = blockIdx.y * 32;
    int tx = threadIdx.x, ty = threadIdx.y;   // 32 x 8
#pragma unroll
    for (int i = 0; i < 32; i += 8) {
        int k = kx + ty + i;
        if (k < K) tile[ty + i][tx] = W[(size_t)k * 1024 + ny + tx];
    }
    __syncthreads();
#pragma unroll
    for (int i = 0; i < 32; i += 8) {
        int n = ny + ty + i, k = kx + tx;
        if (k < K) WT[(size_t)n * K + k] = tile[tx][ty + i];
    }
}

// ---------------- GEMV: out[i] = A[i,:1024] . W + b[0] ----------------
__global__ void gemv1024(const float* __restrict__ A, const float* __restrict__ W,
                         const float* __restrict__ b, float* __restrict__ out, int M)
{
    int warp = (blockIdx.x * blockDim.x + threadIdx.x) >> 5;
    int lane = threadIdx.x & 31;
    if (warp >= M) return;
    const float4* a = (const float4*)(A + (size_t)warp * 1024);
    const float4* w4 = (const float4*)W;
    float acc = 0.f;
#pragma unroll
    for (int i = 0; i < 8; i++) {
        int idx = lane + i * 32;
        float4 x = a[idx], y = w4[idx];
        acc += x.x * y.x + x.y * y.y + x.z * y.z + x.w * y.w;
    }
#pragma unroll
    for (int o = 16; o; o >>= 1) acc += __shfl_xor_sync(0xffffffffu, acc, o);
    if (lane == 0) out[warp] = acc + b[0];
}

// ---------------- WB9[b] = width_embed[b] @ W1d + score_b1 ----------------
__global__ void wb9_kernel(const float* __restrict__ width_embed,
                           const float* __restrict__ W1, const float* __restrict__ b1)
{
    int bkt = blockIdx.x;
    int j4 = threadIdx.x;
    float4 acc = ((const float4*)b1)[j4];
#pragma unroll
    for (int k = 0; k < DD; k++) {
        float wv = width_embed[bkt * DD + k];
        float4 ww = ((const float4*)(W1 + (size_t)(2 * SD + ED + k) * HID))[j4];
        acc.x = fmaf(wv, ww.x, acc.x); acc.y = fmaf(wv, ww.y, acc.y);
        acc.z = fmaf(wv, ww.z, acc.z); acc.w = fmaf(wv, ww.w, acc.w);
    }
    ((float4*)(g_WB9 + (size_t)bkt * HID))[j4] = acc;
}

// ---------------- span kernel: writes g_i row + h1 row per span ----------------
__global__ void span_kernel(const float* __restrict__ states,
                            const float* __restrict__ embeds,
                            const float* __restrict__ width_embed,
                            const int* __restrict__ starts,
                            const int* __restrict__ widths,
                            float* __restrict__ gi, float* __restrict__ h1)
{
    const int n = blockIdx.x;
    const int s = starts[n];
    const int w = widths[n];
    const int e = s + w - 1;
    const int bucket = (w >= 1) + (w >= 2) + (w >= 3) + (w >= 4) +
                       (w >= 8) + (w >= 16) + (w >= 32) + (w >= 64);

    float wt[MAXW];
    float mx = -3.4e38f;
#pragma unroll
    for (int i = 0; i < MAXW; i++) {
        int p = s + i; if (p > T_TOK - 1) p = T_TOK - 1;
        float a = (i < w) ? g_attns[p] : -1e30f;
        wt[i] = a;
        mx = fmaxf(mx, a);
    }
    float sum = 0.f;
#pragma unroll
    for (int i = 0; i < MAXW; i++) {
        float v = (i < w) ? expf(wt[i] - mx) : 0.f;
        wt[i] = v; sum += v;
    }
    const float inv = 1.f / sum;

    const int tid = threadIdx.x;   // 256
    float* girow = gi + (size_t)n * GI;

    ((float4*)girow)[tid] = ((const float4*)(states + (size_t)s * SD))[tid];
    ((float4*)(girow + SD))[tid] = ((const float4*)(states + (size_t)e * SD))[tid];

    if (tid < 128) {
        float4 acc = make_float4(0.f, 0.f, 0.f, 0.f);
#pragma unroll
        for (int i = 0; i < MAXW; i++) {
            if (i < w) {
                float4 v = ((const float4*)(embeds + (size_t)(s + i) * ED))[tid];
                float ww = wt[i] * inv;
                acc.x = fmaf(ww, v.x, acc.x); acc.y = fmaf(ww, v.y, acc.y);
                acc.z = fmaf(ww, v.z, acc.z); acc.w = fmaf(ww, v.w, acc.w);
            }
        }
        ((float4*)(girow + 2 * SD))[tid] = acc;
    } else if (tid < 128 + DD) {
        int j = tid - 128;
        girow[2 * SD + ED + j] = width_embed[bucket * DD + j];
    }

    {
        float4 a = ((const float4*)(g_P1 + (size_t)s * HID))[tid];
        float4 b = ((const float4*)(g_P2 + (size_t)e * HID))[tid];
        float4 c = ((const float4*)(g_WB9 + (size_t)bucket * HID))[tid];
        float4 acc = make_float4(a.x + b.x + c.x, a.y + b.y + c.y,
                                 a.z + b.z + c.z, a.w + b.w + c.w);
#pragma unroll
        for (int i = 0; i < MAXW; i++) {
            if (i < w) {
                float4 v = ((const float4*)(g_E1 + (size_t)(s + i) * HID))[tid];
                float ww = wt[i] * inv;
                acc.x = fmaf(ww, v.x, acc.x); acc.y = fmaf(ww, v.y, acc.y);
                acc.z = fmaf(ww, v.z, acc.z); acc.w = fmaf(ww, v.w, acc.w);
            }
        }
        acc.x = fmaxf(acc.x, 0.f); acc.y = fmaxf(acc.y, 0.f);
        acc.z = fmaxf(acc.z, 0.f); acc.w = fmaxf(acc.w, 0.f);
        ((float4*)(h1 + (size_t)n * HID))[tid] = acc;
    }
}

// ---------------- launcher ----------------
extern "C" void kernel_launch(void* const* d_in, const int* in_sizes, int n_in,
                              void* d_out, int out_size)
{
    const float* states = (const float*)d_in[0];
    const float* embeds = (const float*)d_in[1];
    const float* aW1 = (const float*)d_in[2];
    const float* ab1 = (const float*)d_in[3];
    const float* aW2 = (const float*)d_in[4];
    const float* ab2 = (const float*)d_in[5];
    const float* aW3 = (const float*)d_in[6];
    const float* ab3 = (const float*)d_in[7];
    const float* sW1 = (const float*)d_in[8];
    const float* sb1 = (const float*)d_in[9];
    const float* sW2 = (const float*)d_in[10];
    const float* sb2 = (const float*)d_in[11];
    const float* sW3 = (const float*)d_in[12];
    const float* sb3 = (const float*)d_in[13];
    const float* wemb = (const float*)d_in[14];
    const int* starts = (const int*)d_in[15];
    const int* widths = (const int*)d_in[16];

    float* out = (float*)d_out;
    float* gi = out;
    float* scores = out + (size_t)NSPAN * GI;

    float *A1, *A2, *attns, *P1, *P2, *E1, *h1, *h2;
    float *WTa1, *WTa2, *WTp1, *WTp2, *WTe1, *WTs2;
    cudaGetSymbolAddress((void**)&A1, g_A1);
    cudaGetSymbolAddress((void**)&A2, g_A2);
    cudaGetSymbolAddress((void**)&attns, g_attns);
    cudaGetSymbolAddress((void**)&P1, g_P1);
    cudaGetSymbolAddress((void**)&P2, g_P2);
    cudaGetSymbolAddress((void**)&E1, g_E1);
    cudaGetSymbolAddress((void**)&h1, g_h1);
    cudaGetSymbolAddress((void**)&h2, g_h2);
    cudaGetSymbolAddress((void**)&WTa1, g_WTa1);
    cudaGetSymbolAddress((void**)&WTa2, g_WTa2);
    cudaGetSymbolAddress((void**)&WTp1, g_WTp1);
    cudaGetSymbolAddress((void**)&WTp2, g_WTp2);
    cudaGetSymbolAddress((void**)&WTe1, g_WTe1);
    cudaGetSymbolAddress((void**)&WTs2, g_WTs2);

    cudaFuncSetAttribute(hgemm_x3, cudaFuncAttributeMaxDynamicSharedMemorySize, GEMM_SMEM);

    dim3 tb(32, 8);
    transpose_kn<<<dim3(32, 32), tb>>>(aW1, WTa1, SD);
    transpose_kn<<<dim3(32, 32), tb>>>(aW2, WTa2, HID);
    transpose_kn<<<dim3(32, 32), tb>>>(sW1, WTp1, SD);
    transpose_kn<<<dim3(32, 32), tb>>>(sW1 + (size_t)SD * HID, WTp2, SD);
    transpose_kn<<<dim3(16, 32), tb>>>(sW1 + (size_t)2 * SD * HID, WTe1, ED);
    transpose_kn<<<dim3(32, 32), tb>>>(sW2, WTs2, HID);
    wb9_kernel<<<9, 256>>>(wemb, sW1, sb1);

    // grid: x = N-tiles (8) fastest, y = M-tiles -> consecutive CTAs share A tile (L2 reuse)
    dim3 gT(1024 / TN, (T_TOK + TM - 1) / TM);   // 8 x 32
    // token attention MLP (fp16x3 -> fp32-accurate)
    hgemm_x3<<<gT, 256, GEMM_SMEM>>>(states, WTa1, ab1, A1, T_TOK, SD, 1);
    hgemm_x3<<<gT, 256, GEMM_SMEM>>>(A1, WTa2, ab2, A2, T_TOK, HID, 1);
    gemv1024<<<(T_TOK * 32 + 255) / 256, 256>>>(A2, aW3, ab3, attns, T_TOK);

    // score layer-1 decomposition precompute (token-level)
    hgemm_x3<<<gT, 256, GEMM_SMEM>>>(states, WTp1, nullptr, P1, T_TOK, SD, 0);
    hgemm_x3<<<gT, 256, GEMM_SMEM>>>(states, WTp2, nullptr, P2, T_TOK, SD, 0);
    hgemm_x3<<<gT, 256, GEMM_SMEM>>>(embeds, WTe1, nullptr, E1, T_TOK, ED, 0);

    // per-span: g_i output + fused layer-1 (h1)
    span_kernel<<<NSPAN, 256>>>(states, embeds, wemb, starts, widths, gi, h1);

    // score layer-2 + layer-3
    dim3 gN(1024 / TN, (NSPAN + TM - 1) / TM);   // 8 x 320
    hgemm_x3<<<gN, 256, GEMM_SMEM>>>(h1, WTs2, sb2, h2, NSPAN, HID, 1);
    gemv1024<<<((NSPAN * 32) + 255) / 256, 256>>>(h2, sW3, sb3, scores, NSPAN);
}

// round 7
// speedup vs baseline: 2.1635x; 1.5866x over previous
#include <cuda_runtime.h>
#include <cuda_fp16.h>
#include <cstdint>

#define T_TOK 4096
#define SD    1024
#define ED    512
#define DD    20
#define HID   1024
#define GI    2580
#define NSPAN 40915
#define MAXW  10

// ---------------- scratch (static device globals; no allocations) ----------------
__device__ __half g_A1h[(size_t)T_TOK * HID];
__device__ __half g_A1l[(size_t)T_TOK * HID];
__device__ float  g_A2[(size_t)T_TOK * HID];
__device__ float  g_attns[T_TOK];
__device__ float  g_P1[(size_t)T_TOK * HID];
__device__ float  g_P2[(size_t)T_TOK * HID];
__device__ float  g_E1[(size_t)T_TOK * HID];
__device__ float  g_WB9[9 * HID];
__device__ __half g_h1h[(size_t)NSPAN * HID];
__device__ __half g_h1l[(size_t)NSPAN * HID];
__device__ float  g_h2[(size_t)NSPAN * HID];
// split activations
__device__ __half g_Sth[(size_t)T_TOK * SD];
__device__ __half g_Stl[(size_t)T_TOK * SD];
__device__ __half g_Emh[(size_t)T_TOK * ED];
__device__ __half g_Eml[(size_t)T_TOK * ED];
// transposed+split weights [N=1024 rows, K cols], hi/lo __half
__device__ __half g_Wa1h[(size_t)HID * SD], g_Wa1l[(size_t)HID * SD];
__device__ __half g_Wa2h[(size_t)HID * HID], g_Wa2l[(size_t)HID * HID];
__device__ __half g_Wp1h[(size_t)HID * SD], g_Wp1l[(size_t)HID * SD];
__device__ __half g_Wp2h[(size_t)HID * SD], g_Wp2l[(size_t)HID * SD];
__device__ __half g_We1h[(size_t)HID * ED], g_We1l[(size_t)HID * ED];
__device__ __half g_Ws2h[(size_t)HID * HID], g_Ws2l[(size_t)HID * HID];

// ======================= helpers =======================
__device__ __forceinline__ uint32_t smem_u32(const void* p) {
    uint32_t a;
    asm("{ .reg .u64 t; cvta.to.shared.u64 t, %1; cvt.u32.u64 %0, t; }" : "=r"(a) : "l"(p));
    return a;
}
__device__ __forceinline__ void ldmx4(uint32_t* r, uint32_t addr) {
    asm volatile("ldmatrix.sync.aligned.m8n8.x4.shared.b16 {%0,%1,%2,%3}, [%4];"
                 : "=r"(r[0]), "=r"(r[1]), "=r"(r[2]), "=r"(r[3]) : "r"(addr));
}
__device__ __forceinline__ void mma16816(float* c, const uint32_t* a, const uint32_t* b) {
    asm volatile(
        "mma.sync.aligned.m16n8k16.row.col.f32.f16.f16.f32 "
        "{%0,%1,%2,%3}, {%4,%5,%6,%7}, {%8,%9}, {%0,%1,%2,%3};"
        : "+f"(c[0]), "+f"(c[1]), "+f"(c[2]), "+f"(c[3])
        : "r"(a[0]), "r"(a[1]), "r"(a[2]), "r"(a[3]), "r"(b[0]), "r"(b[1]));
}
__device__ __forceinline__ void cp16(uint32_t dst, const void* src, bool ok) {
    int sz = ok ? 16 : 0;
    asm volatile("cp.async.ca.shared.global [%0], [%1], 16, %2;" :: "r"(dst), "l"(src), "r"(sz));
}
#define CP_COMMIT() asm volatile("cp.async.commit_group;" ::: "memory")
#define CP_WAIT(n)  asm volatile("cp.async.wait_group %0;" :: "n"(n) : "memory")

// ======================= fp16x3 mma.sync GEMM, cp.async 3-stage =============
// C[M,1024] = A @ B^T with A,B pre-split into fp16 hi/lo ([rows,K] K-major).
// Accuracy: hh + hl + lh (Dekker) == fp32-equivalent.
#define TM 128
#define TN 128
#define KC 32
#define RS 80                       // smem row stride (64B data + 16B pad)
#define TILE_B (128 * RS)           // 10240
#define STAGE_B (4 * TILE_B)        // Ah Al Bh Bl = 40960
#define STAGES 3
#define GEMM_SMEM (STAGES * STAGE_B)  // 122880

__global__ __launch_bounds__(256, 1) void hgemm_x3(
    const __half* __restrict__ Ah, const __half* __restrict__ Al,
    const __half* __restrict__ Bh, const __half* __restrict__ Bl,
    const float* __restrict__ bias,
    float* __restrict__ C, __half* __restrict__ Ch, __half* __restrict__ Cl,
    int M, int K, int relu)
{
    extern __shared__ char smem[];
    const uint32_t sbase = smem_u32(smem);

    const int tid = threadIdx.x;
    const int lane = tid & 31;
    const int wid = tid >> 5;
    const int wm = (wid >> 2) * 64;
    const int wn = (wid & 3) * 32;
    const int bn = blockIdx.x * TN;     // N fastest -> A tile L2 reuse
    const int bm = blockIdx.y * TM;

    // cp.async plan: 512 16B-units per operand-buffer; 2 per thread
    uint32_t soff[2]; size_t agoff[2], bgoff[2]; bool aok[2];
#pragma unroll
    for (int i = 0; i < 2; i++) {
        int u = tid + 256 * i;
        int row = u >> 2, seg = u & 3;
        soff[i] = (uint32_t)(row * RS + seg * 16);
        int ar = bm + row; aok[i] = ar < M; if (ar > M - 1) ar = M - 1;
        agoff[i] = (size_t)ar * K + seg * 8;
        bgoff[i] = (size_t)(bn + row) * K + seg * 8;
    }

    const int nchunks = K / KC;

    // prologue: issue STAGES-1 stages
#pragma unroll
    for (int s = 0; s < STAGES - 1; s++) {
        uint32_t sb = sbase + s * STAGE_B;
        int kc = s * KC;
#pragma unroll
        for (int i = 0; i < 2; i++) {
            cp16(sb + soff[i],              Ah + agoff[i] + kc, aok[i]);
            cp16(sb + TILE_B + soff[i],     Al + agoff[i] + kc, aok[i]);
            cp16(sb + 2 * TILE_B + soff[i], Bh + bgoff[i] + kc, true);
            cp16(sb + 3 * TILE_B + soff[i], Bl + bgoff[i] + kc, true);
        }
        CP_COMMIT();
    }

    float acc[4][4][4];
#pragma unroll
    for (int mi = 0; mi < 4; mi++)
#pragma unroll
        for (int ni = 0; ni < 4; ni++)
#pragma unroll
            for (int q = 0; q < 4; q++) acc[mi][ni][q] = 0.f;

    const int lr = lane & 15;
    const int ch = (lane >> 4) * 16;

    int st = 0;                      // stage of current chunk
    int st_issue = STAGES - 1;       // stage to fill next
    for (int c = 0; c < nchunks; ++c) {
        CP_WAIT(STAGES - 2);
        __syncthreads();

        // issue chunk c+STAGES-1 into the stage consumed at chunk c-1
        if (c + STAGES - 1 < nchunks) {
            uint32_t sb = sbase + st_issue * STAGE_B;
            int kc = (c + STAGES - 1) * KC;
#pragma unroll
            for (int i = 0; i < 2; i++) {
                cp16(sb + soff[i],              Ah + agoff[i] + kc, aok[i]);
                cp16(sb + TILE_B + soff[i],     Al + agoff[i] + kc, aok[i]);
                cp16(sb + 2 * TILE_B + soff[i], Bh + bgoff[i] + kc, true);
                cp16(sb + 3 * TILE_B + soff[i], Bl + bgoff[i] + kc, true);
            }
        }
        CP_COMMIT();   // commit even when empty to keep wait_group accounting fixed
        st_issue = (st_issue + 1 == STAGES) ? 0 : st_issue + 1;

        const uint32_t sb = sbase + st * STAGE_B;
        st = (st + 1 == STAGES) ? 0 : st + 1;
#pragma unroll
        for (int ks = 0; ks < 2; ks++) {
            const uint32_t colb = (uint32_t)(ks * 32 + ch);
            uint32_t aH[4][4], aL[4][4], bH[4][2], bL[4][2];
#pragma unroll
            for (int mi = 0; mi < 4; mi++) {
                uint32_t rowo = (uint32_t)((wm + mi * 16 + lr) * RS) + colb;
                ldmx4(aH[mi], sb + rowo);
                ldmx4(aL[mi], sb + TILE_B + rowo);
            }
#pragma unroll
            for (int g = 0; g < 2; g++) {
                uint32_t rowo = (uint32_t)((wn + g * 16 + lr) * RS) + colb;
                uint32_t r[4];
                ldmx4(r, sb + 2 * TILE_B + rowo);
                bH[g * 2][0] = r[0]; bH[g * 2][1] = r[2];
                bH[g * 2 + 1][0] = r[1]; bH[g * 2 + 1][1] = r[3];
                ldmx4(r, sb + 3 * TILE_B + rowo);
                bL[g * 2][0] = r[0]; bL[g * 2][1] = r[2];
                bL[g * 2 + 1][0] = r[1]; bL[g * 2 + 1][1] = r[3];
            }
#pragma unroll
            for (int mi = 0; mi < 4; mi++)
#pragma unroll
                for (int ni = 0; ni < 4; ni++) {
                    mma16816(acc[mi][ni], aH[mi], bH[ni]);
                    mma16816(acc[mi][ni], aH[mi], bL[ni]);
                    mma16816(acc[mi][ni], aL[mi], bH[ni]);
                }
        }
    }

    // epilogue
    const int mrow = lane >> 2;
    const int ncol = (lane & 3) * 2;
#pragma unroll
    for (int mi = 0; mi < 4; mi++) {
#pragma unroll
        for (int ni = 0; ni < 4; ni++) {
            int n0 = bn + wn + ni * 8 + ncol;
            float b0 = bias ? bias[n0] : 0.f;
            float b1 = bias ? bias[n0 + 1] : 0.f;
#pragma unroll
            for (int half_ : {0, 1}) {
                int m = bm + wm + mi * 16 + mrow + half_ * 8;
                if (m < M) {
                    float vx = acc[mi][ni][half_ * 2 + 0] + b0;
                    float vy = acc[mi][ni][half_ * 2 + 1] + b1;
                    if (relu) { vx = fmaxf(vx, 0.f); vy = fmaxf(vy, 0.f); }
                    if (C) *(float2*)(C + (size_t)m * 1024 + n0) = make_float2(vx, vy);
                    if (Ch) {
                        __half2 h = __floats2half2_rn(vx, vy);
                        float2 hf = __half22float2(h);
                        __half2 l = __floats2half2_rn(vx - hf.x, vy - hf.y);
                        *(__half2*)(Ch + (size_t)m * 1024 + n0) = h;
                        *(__half2*)(Cl + (size_t)m * 1024 + n0) = l;
                    }
                }
            }
        }
    }
}

// ------------- transpose+split: W[k,1024] -> WTh/WTl [n,K] __half -------------
__global__ void transpose_split(const float* __restrict__ W,
                                __half* __restrict__ Hh, __half* __restrict__ Hl, int K)
{
    __shared__ float tile[32][33];
    int kx = blockIdx.x * 32, ny = blockIdx.y * 32;
    int tx = threadIdx.x, ty = threadIdx.y;   // 32 x 8
#pragma unroll
    for (int i = 0; i < 32; i += 8) {
        int k = kx + ty + i;
        if (k < K) tile[ty + i][tx] = W[(size_t)k * 1024 + ny + tx];
    }
    __syncthreads();
#pragma unroll
    for (int i = 0; i < 32; i += 8) {
        int n = ny + ty + i, k = kx + tx;
        if (k < K) {
            float v = tile[tx][ty + i];
            __half h = __float2half_rn(v);
            Hh[(size_t)n * K + k] = h;
            Hl[(size_t)n * K + k] = __float2half_rn(v - __half2float(h));
        }
    }
}

// ------------- split activations: X fp32 -> Xh, Xl fp16 -------------
__global__ void split_act(const float* __restrict__ X,
                          __half* __restrict__ Xh, __half* __restrict__ Xl, int n4)
{
    int i = blockIdx.x * blockDim.x + threadIdx.x;
    if (i >= n4) return;
    float4 v = ((const float4*)X)[i];
    __half2 h01 = __floats2half2_rn(v.x, v.y);
    __half2 h23 = __floats2half2_rn(v.z, v.w);
    float2 f01 = __half22float2(h01);
    float2 f23 = __half22float2(h23);
    __half2 l01 = __floats2half2_rn(v.x - f01.x, v.y - f01.y);
    __half2 l23 = __floats2half2_rn(v.z - f23.x, v.w - f23.y);
    ((__half2*)Xh)[i * 2] = h01; ((__half2*)Xh)[i * 2 + 1] = h23;
    ((__half2*)Xl)[i * 2] = l01; ((__half2*)Xl)[i * 2 + 1] = l23;
}

// ---------------- GEMV: out[i] = A[i,:1024] . W + b[0] ----------------
__global__ void gemv1024(const float* __restrict__ A, const float* __restrict__ W,
                         const float* __restrict__ b, float* __restrict__ out, int M)
{
    int warp = (blockIdx.x * blockDim.x + threadIdx.x) >> 5;
    int lane = threadIdx.x & 31;
    if (warp >= M) return;
    const float4* a = (const float4*)(A + (size_t)warp * 1024);
    const float4* w4 = (const float4*)W;
    float acc = 0.f;
#pragma unroll
    for (int i = 0; i < 8; i++) {
        int idx = lane + i * 32;
        float4 x = a[idx], y = w4[idx];
        acc += x.x * y.x + x.y * y.y + x.z * y.z + x.w * y.w;
    }
#pragma unroll
    for (int o = 16; o; o >>= 1) acc += __shfl_xor_sync(0xffffffffu, acc, o);
    if (lane == 0) out[warp] = acc + b[0];
}

// ---------------- WB9[b] = width_embed[b] @ W1d + score_b1 ----------------
__global__ void wb9_kernel(const float* __restrict__ width_embed,
                           const float* __restrict__ W1, const float* __restrict__ b1)
{
    int bkt = blockIdx.x;
    int j4 = threadIdx.x;
    float4 acc = ((const float4*)b1)[j4];
#pragma unroll
    for (int k = 0; k < DD; k++) {
        float wv = width_embed[bkt * DD + k];
        float4 ww = ((const float4*)(W1 + (size_t)(2 * SD + ED + k) * HID))[j4];
        acc.x = fmaf(wv, ww.x, acc.x); acc.y = fmaf(wv, ww.y, acc.y);
        acc.z = fmaf(wv, ww.z, acc.z); acc.w = fmaf(wv, ww.w, acc.w);
    }
    ((float4*)(g_WB9 + (size_t)bkt * HID))[j4] = acc;
}

// ---------------- span kernel: g_i row (fp32) + h1 row (split fp16) -----------
__global__ void span_kernel(const float* __restrict__ states,
                            const float* __restrict__ embeds,
                            const float* __restrict__ width_embed,
                            const int* __restrict__ starts,
                            const int* __restrict__ widths,
                            float* __restrict__ gi,
                            __half* __restrict__ h1h, __half* __restrict__ h1l)
{
    const int n = blockIdx.x;
    const int s = starts[n];
    const int w = widths[n];
    const int e = s + w - 1;
    const int bucket = (w >= 1) + (w >= 2) + (w >= 3) + (w >= 4) +
                       (w >= 8) + (w >= 16) + (w >= 32) + (w >= 64);

    float wt[MAXW];
    float mx = -3.4e38f;
#pragma unroll
    for (int i = 0; i < MAXW; i++) {
        int p = s + i; if (p > T_TOK - 1) p = T_TOK - 1;
        float a = (i < w) ? g_attns[p] : -1e30f;
        wt[i] = a;
        mx = fmaxf(mx, a);
    }
    float sum = 0.f;
#pragma unroll
    for (int i = 0; i < MAXW; i++) {
        float v = (i < w) ? expf(wt[i] - mx) : 0.f;
        wt[i] = v; sum += v;
    }
    const float inv = 1.f / sum;

    const int tid = threadIdx.x;   // 256
    float* girow = gi + (size_t)n * GI;

    ((float4*)girow)[tid] = ((const float4*)(states + (size_t)s * SD))[tid];
    ((float4*)(girow + SD))[tid] = ((const float4*)(states + (size_t)e * SD))[tid];

    if (tid < 128) {
        float4 acc = make_float4(0.f, 0.f, 0.f, 0.f);
#pragma unroll
        for (int i = 0; i < MAXW; i++) {
            if (i < w) {
                float4 v = ((const float4*)(embeds + (size_t)(s + i) * ED))[tid];
                float ww = wt[i] * inv;
                acc.x = fmaf(ww, v.x, acc.x); acc.y = fmaf(ww, v.y, acc.y);
                acc.z = fmaf(ww, v.z, acc.z); acc.w = fmaf(ww, v.w, acc.w);
            }
        }
        ((float4*)(girow + 2 * SD))[tid] = acc;
    } else if (tid < 128 + DD) {
        int j = tid - 128;
        girow[2 * SD + ED + j] = width_embed[bucket * DD + j];
    }

    {
        float4 a = ((const float4*)(g_P1 + (size_t)s * HID))[tid];
        float4 b = ((const float4*)(g_P2 + (size_t)e * HID))[tid];
        float4 c = ((const float4*)(g_WB9 + (size_t)bucket * HID))[tid];
        float4 acc = make_float4(a.x + b.x + c.x, a.y + b.y + c.y,
                                 a.z + b.z + c.z, a.w + b.w + c.w);
#pragma unroll
        for (int i = 0; i < MAXW; i++) {
            if (i < w) {
                float4 v = ((const float4*)(g_E1 + (size_t)(s + i) * HID))[tid];
                float ww = wt[i] * inv;
                acc.x = fmaf(ww, v.x, acc.x); acc.y = fmaf(ww, v.y, acc.y);
                acc.z = fmaf(ww, v.z, acc.z); acc.w = fmaf(ww, v.w, acc.w);
            }
        }
        acc.x = fmaxf(acc.x, 0.f); acc.y = fmaxf(acc.y, 0.f);
        acc.z = fmaxf(acc.z, 0.f); acc.w = fmaxf(acc.w, 0.f);
        // split write (hi/lo fp16)
        __half2 h01 = __floats2half2_rn(acc.x, acc.y);
        __half2 h23 = __floats2half2_rn(acc.z, acc.w);
        float2 f01 = __half22float2(h01);
        float2 f23 = __half22float2(h23);
        __half2 l01 = __floats2half2_rn(acc.x - f01.x, acc.y - f01.y);
        __half2 l23 = __floats2half2_rn(acc.z - f23.x, acc.w - f23.y);
        ((__half2*)(h1h + (size_t)n * HID))[tid * 2] = h01;
        ((__half2*)(h1h + (size_t)n * HID))[tid * 2 + 1] = h23;
        ((__half2*)(h1l + (size_t)n * HID))[tid * 2] = l01;
        ((__half2*)(h1l + (size_t)n * HID))[tid * 2 + 1] = l23;
    }
}

// ---------------- launcher ----------------
extern "C" void kernel_launch(void* const* d_in, const int* in_sizes, int n_in,
                              void* d_out, int out_size)
{
    const float* states = (const float*)d_in[0];
    const float* embeds = (const float*)d_in[1];
    const float* aW1 = (const float*)d_in[2];
    const float* ab1 = (const float*)d_in[3];
    const float* aW2 = (const float*)d_in[4];
    const float* ab2 = (const float*)d_in[5];
    const float* aW3 = (const float*)d_in[6];
    const float* ab3 = (const float*)d_in[7];
    const float* sW1 = (const float*)d_in[8];
    const float* sb1 = (const float*)d_in[9];
    const float* sW2 = (const float*)d_in[10];
    const float* sb2 = (const float*)d_in[11];
    const float* sW3 = (const float*)d_in[12];
    const float* sb3 = (const float*)d_in[13];
    const float* wemb = (const float*)d_in[14];
    const int* starts = (const int*)d_in[15];
    const int* widths = (const int*)d_in[16];

    float* out = (float*)d_out;
    float* gi = out;
    float* scores = out + (size_t)NSPAN * GI;

    float *A2, *attns, *P1, *P2, *E1, *h2;
    __half *A1h, *A1l, *h1h, *h1l, *Sth, *Stl, *Emh, *Eml;
    __half *Wa1h, *Wa1l, *Wa2h, *Wa2l, *Wp1h, *Wp1l, *Wp2h, *Wp2l, *We1h, *We1l, *Ws2h, *Ws2l;
    cudaGetSymbolAddress((void**)&A2, g_A2);
    cudaGetSymbolAddress((void**)&attns, g_attns);
    cudaGetSymbolAddress((void**)&P1, g_P1);
    cudaGetSymbolAddress((void**)&P2, g_P2);
    cudaGetSymbolAddress((void**)&E1, g_E1);
    cudaGetSymbolAddress((void**)&h2, g_h2);
    cudaGetSymbolAddress((void**)&A1h, g_A1h);
    cudaGetSymbolAddress((void**)&A1l, g_A1l);
    cudaGetSymbolAddress((void**)&h1h, g_h1h);
    cudaGetSymbolAddress((void**)&h1l, g_h1l);
    cudaGetSymbolAddress((void**)&Sth, g_Sth);
    cudaGetSymbolAddress((void**)&Stl, g_Stl);
    cudaGetSymbolAddress((void**)&Emh, g_Emh);
    cudaGetSymbolAddress((void**)&Eml, g_Eml);
    cudaGetSymbolAddress((void**)&Wa1h, g_Wa1h);
    cudaGetSymbolAddress((void**)&Wa1l, g_Wa1l);
    cudaGetSymbolAddress((void**)&Wa2h, g_Wa2h);
    cudaGetSymbolAddress((void**)&Wa2l, g_Wa2l);
    cudaGetSymbolAddress((void**)&Wp1h, g_Wp1h);
    cudaGetSymbolAddress((void**)&Wp1l, g_Wp1l);
    cudaGetSymbolAddress((void**)&Wp2h, g_Wp2h);
    cudaGetSymbolAddress((void**)&Wp2l, g_Wp2l);
    cudaGetSymbolAddress((void**)&We1h, g_We1h);
    cudaGetSymbolAddress((void**)&We1l, g_We1l);
    cudaGetSymbolAddress((void**)&Ws2h, g_Ws2h);
    cudaGetSymbolAddress((void**)&Ws2l, g_Ws2l);

    cudaFuncSetAttribute(hgemm_x3, cudaFuncAttributeMaxDynamicSharedMemorySize, GEMM_SMEM);

    dim3 tb(32, 8);
    // launches 1-5 (small), so that launch #6 (ncu -s 5 -c 1) is a GEMM
    split_act<<<(T_TOK * SD / 4 + 255) / 256, 256>>>(states, Sth, Stl, T_TOK * SD / 4);
    split_act<<<(T_TOK * ED / 4 + 255) / 256, 256>>>(embeds, Emh, Eml, T_TOK * ED / 4);
    wb9_kernel<<<9, 256>>>(wemb, sW1, sb1);
    transpose_split<<<dim3(32, 32), tb>>>(aW1, Wa1h, Wa1l, SD);
    transpose_split<<<dim3(32, 32), tb>>>(aW2, Wa2h, Wa2l, HID);

    dim3 gT(1024 / TN, (T_TOK + TM - 1) / TM);   // 8 x 32
    // launch #6: representative GEMM for ncu
    hgemm_x3<<<gT, 256, GEMM_SMEM>>>(Sth, Stl, Wa1h, Wa1l, ab1, nullptr, A1h, A1l, T_TOK, SD, 1);

    transpose_split<<<dim3(32, 32), tb>>>(sW1, Wp1h, Wp1l, SD);
    transpose_split<<<dim3(32, 32), tb>>>(sW1 + (size_t)SD * HID, Wp2h, Wp2l, SD);
    transpose_split<<<dim3(16, 32), tb>>>(sW1 + (size_t)2 * SD * HID, We1h, We1l, ED);
    transpose_split<<<dim3(32, 32), tb>>>(sW2, Ws2h, Ws2l, HID);

    hgemm_x3<<<gT, 256, GEMM_SMEM>>>(A1h, A1l, Wa2h, Wa2l, ab2, A2, nullptr, nullptr, T_TOK, HID, 1);
    gemv1024<<<(T_TOK * 32 + 255) / 256, 256>>>(A2, aW3, ab3, attns, T_TOK);

    hgemm_x3<<<gT, 256, GEMM_SMEM>>>(Sth, Stl, Wp1h, Wp1l, nullptr, P1, nullptr, nullptr, T_TOK, SD, 0);
    hgemm_x3<<<gT, 256, GEMM_SMEM>>>(Sth, Stl, Wp2h, Wp2l, nullptr, P2, nullptr, nullptr, T_TOK, SD, 0);
    hgemm_x3<<<gT, 256, GEMM_SMEM>>>(Emh, Eml, We1h, We1l, nullptr, E1, nullptr, nullptr, T_TOK, ED, 0);

    span_kernel<<<NSPAN, 256>>>(states, embeds, wemb, starts, widths, gi, h1h, h1l);

    dim3 gN(1024 / TN, (NSPAN + TM - 1) / TM);   // 8 x 320
    hgemm_x3<<<gN, 256, GEMM_SMEM>>>(h1h, h1l, Ws2h, Ws2l, sb2, h2, nullptr, nullptr, NSPAN, HID, 1);
    gemv1024<<<((NSPAN * 32) + 255) / 256, 256>>>(h2, sW3, sb3, scores, NSPAN);
}

// round 8
// speedup vs baseline: 2.1854x; 1.0101x over previous
#include <cuda_runtime.h>
#include <cuda_fp16.h>
#include <cstdint>

#define T_TOK 4096
#define SD    1024
#define ED    512
#define DD    20
#define HID   1024
#define GI    2580
#define NSPAN 40915
#define MAXW  10

// ---------------- scratch (static device globals; no allocations) ----------------
__device__ __half g_A1h[(size_t)T_TOK * HID];
__device__ __half g_A1l[(size_t)T_TOK * HID];
__device__ float  g_attns[T_TOK];
__device__ float  g_P12[(size_t)T_TOK * 2048];
__device__ float  g_E1[(size_t)T_TOK * HID];
__device__ float  g_WB9[9 * HID];
__device__ __half g_h1h[(size_t)NSPAN * HID];
__device__ __half g_h1l[(size_t)NSPAN * HID];
__device__ float  g_part[(size_t)NSPAN * 16];
// split activations
__device__ __half g_Sth[(size_t)T_TOK * SD];
__device__ __half g_Stl[(size_t)T_TOK * SD];
__device__ __half g_Emh[(size_t)T_TOK * ED];
__device__ __half g_Eml[(size_t)T_TOK * ED];
// transposed+split weights [N rows, K cols], hi/lo __half
__device__ __half g_Wa1h[(size_t)HID * SD], g_Wa1l[(size_t)HID * SD];
__device__ __half g_Wa2h[(size_t)HID * HID], g_Wa2l[(size_t)HID * HID];
__device__ __half g_Wp12h[(size_t)2048 * SD], g_Wp12l[(size_t)2048 * SD];
__device__ __half g_We1h[(size_t)HID * ED], g_We1l[(size_t)HID * ED];
__device__ __half g_Ws2h[(size_t)HID * HID], g_Ws2l[(size_t)HID * HID];

// ======================= helpers =======================
__device__ __forceinline__ uint32_t smem_u32(const void* p) {
    uint32_t a;
    asm("{ .reg .u64 t; cvta.to.shared.u64 t, %1; cvt.u32.u64 %0, t; }" : "=r"(a) : "l"(p));
    return a;
}
__device__ __forceinline__ void ldmx4(uint32_t* r, uint32_t addr) {
    asm volatile("ldmatrix.sync.aligned.m8n8.x4.shared.b16 {%0,%1,%2,%3}, [%4];"
                 : "=r"(r[0]), "=r"(r[1]), "=r"(r[2]), "=r"(r[3]) : "r"(addr));
}
__device__ __forceinline__ void mma16816(float* c, const uint32_t* a, const uint32_t* b) {
    asm volatile(
        "mma.sync.aligned.m16n8k16.row.col.f32.f16.f16.f32 "
        "{%0,%1,%2,%3}, {%4,%5,%6,%7}, {%8,%9}, {%0,%1,%2,%3};"
        : "+f"(c[0]), "+f"(c[1]), "+f"(c[2]), "+f"(c[3])
        : "r"(a[0]), "r"(a[1]), "r"(a[2]), "r"(a[3]), "r"(b[0]), "r"(b[1]));
}
__device__ __forceinline__ void cp16(uint32_t dst, const void* src, bool ok) {
    int sz = ok ? 16 : 0;
    asm volatile("cp.async.ca.shared.global [%0], [%1], 16, %2;" :: "r"(dst), "l"(src), "r"(sz));
}
#define CP_COMMIT() asm volatile("cp.async.commit_group;" ::: "memory")
#define CP_WAIT(n)  asm volatile("cp.async.wait_group %0;" :: "n"(n) : "memory")

// ======================= fp16x3 mma.sync GEMM, cp.async 3-stage =============
// C[M,N] = A @ B^T with A,B pre-split into fp16 hi/lo ([rows,K] K-major).
// CTA tile 128x256, warp tile 64x64, KC=32. Accuracy: hh+hl+lh (Dekker).
// Output modes: partials!=0 -> fused relu+dot(w3) partials; Ch!=0 -> split fp16;
// else fp32 C (relu optional), row stride ldc.
#define TM 128
#define TN 256
#define KC 32
#define RS 80
#define A_B (TM * RS)               // 10240
#define B_B (TN * RS)               // 20480
#define STAGE_B (2 * A_B + 2 * B_B) // 61440
#define STAGES 3
#define GEMM_SMEM (STAGES * STAGE_B)  // 184320

__global__ __launch_bounds__(256, 1) void hgemm_x3(
    const __half* __restrict__ Ah, const __half* __restrict__ Al,
    const __half* __restrict__ Bh, const __half* __restrict__ Bl,
    const float* __restrict__ bias,
    float* __restrict__ C, __half* __restrict__ Ch, __half* __restrict__ Cl,
    const float* __restrict__ w3, float* __restrict__ partials,
    int M, int K, int ldc, int relu)
{
    extern __shared__ char smem[];
    const uint32_t sbase = smem_u32(smem);

    const int tid = threadIdx.x;
    const int lane = tid & 31;
    const int wid = tid >> 5;
    const int wm = (wid >> 2) * 64;
    const int wn = (wid & 3) * 64;
    const int bn = blockIdx.x * TN;     // N fastest -> A tile L2 reuse
    const int bm = blockIdx.y * TM;

    // cp.async plan: A 512 16B-units (2/thread), B 1024 units (4/thread)
    uint32_t aoffs[2]; size_t agoff[2]; bool aok[2];
#pragma unroll
    for (int i = 0; i < 2; i++) {
        int u = tid + 256 * i;
        int row = u >> 2, seg = u & 3;
        aoffs[i] = (uint32_t)(row * RS + seg * 16);
        int ar = bm + row; aok[i] = ar < M; if (ar > M - 1) ar = M - 1;
        agoff[i] = (size_t)ar * K + seg * 8;
    }
    uint32_t boffs[4]; size_t bgoff[4];
#pragma unroll
    for (int i = 0; i < 4; i++) {
        int u = tid + 256 * i;
        int row = u >> 2, seg = u & 3;
        boffs[i] = (uint32_t)(row * RS + seg * 16);
        bgoff[i] = (size_t)(bn + row) * K + seg * 8;
    }

    const int nchunks = K / KC;

    // prologue: issue STAGES-1 stages
#pragma unroll
    for (int s = 0; s < STAGES - 1; s++) {
        uint32_t sb = sbase + s * STAGE_B;
        int kc = s * KC;
#pragma unroll
        for (int i = 0; i < 2; i++) {
            cp16(sb + aoffs[i],        Ah + agoff[i] + kc, aok[i]);
            cp16(sb + A_B + aoffs[i],  Al + agoff[i] + kc, aok[i]);
        }
#pragma unroll
        for (int i = 0; i < 4; i++) {
            cp16(sb + 2 * A_B + boffs[i],       Bh + bgoff[i] + kc, true);
            cp16(sb + 2 * A_B + B_B + boffs[i], Bl + bgoff[i] + kc, true);
        }
        CP_COMMIT();
    }

    float acc[4][8][4];
#pragma unroll
    for (int mi = 0; mi < 4; mi++)
#pragma unroll
        for (int ni = 0; ni < 8; ni++)
#pragma unroll
            for (int q = 0; q < 4; q++) acc[mi][ni][q] = 0.f;

    const int lr = lane & 15;
    const int ch = (lane >> 4) * 16;

    int st = 0;
    int st_issue = STAGES - 1;
    for (int c = 0; c < nchunks; ++c) {
        CP_WAIT(STAGES - 2);
        __syncthreads();

        if (c + STAGES - 1 < nchunks) {
            uint32_t sb = sbase + st_issue * STAGE_B;
            int kc = (c + STAGES - 1) * KC;
#pragma unroll
            for (int i = 0; i < 2; i++) {
                cp16(sb + aoffs[i],       Ah + agoff[i] + kc, aok[i]);
                cp16(sb + A_B + aoffs[i], Al + agoff[i] + kc, aok[i]);
            }
#pragma unroll
            for (int i = 0; i < 4; i++) {
                cp16(sb + 2 * A_B + boffs[i],       Bh + bgoff[i] + kc, true);
                cp16(sb + 2 * A_B + B_B + boffs[i], Bl + bgoff[i] + kc, true);
            }
        }
        CP_COMMIT();
        st_issue = (st_issue + 1 == STAGES) ? 0 : st_issue + 1;

        const uint32_t sb = sbase + st * STAGE_B;
        st = (st + 1 == STAGES) ? 0 : st + 1;
#pragma unroll
        for (int ks = 0; ks < 2; ks++) {
            const uint32_t colb = (uint32_t)(ks * 32 + ch);
            uint32_t aH[4][4], aL[4][4];
#pragma unroll
            for (int mi = 0; mi < 4; mi++) {
                uint32_t rowo = (uint32_t)((wm + mi * 16 + lr) * RS) + colb;
                ldmx4(aH[mi], sb + rowo);
                ldmx4(aL[mi], sb + A_B + rowo);
            }
#pragma unroll
            for (int h = 0; h < 2; h++) {
                uint32_t bH[4][2], bL[4][2];
#pragma unroll
                for (int g = 0; g < 2; g++) {
                    uint32_t rowo = (uint32_t)((wn + h * 32 + g * 16 + lr) * RS) + colb;
                    uint32_t r[4];
                    ldmx4(r, sb + 2 * A_B + rowo);
                    bH[g * 2][0] = r[0]; bH[g * 2][1] = r[2];
                    bH[g * 2 + 1][0] = r[1]; bH[g * 2 + 1][1] = r[3];
                    ldmx4(r, sb + 2 * A_B + B_B + rowo);
                    bL[g * 2][0] = r[0]; bL[g * 2][1] = r[2];
                    bL[g * 2 + 1][0] = r[1]; bL[g * 2 + 1][1] = r[3];
                }
#pragma unroll
                for (int mi = 0; mi < 4; mi++)
#pragma unroll
                    for (int ni = 0; ni < 4; ni++) {
                        float* a_ = acc[mi][h * 4 + ni];
                        mma16816(a_, aH[mi], bH[ni]);
                        mma16816(a_, aH[mi], bL[ni]);
                        mma16816(a_, aL[mi], bH[ni]);
                    }
            }
        }
    }

    // ---------------- epilogue ----------------
    const int mrow = lane >> 2;
    const int ncol = (lane & 3) * 2;

    if (partials) {
        // fused: relu(acc+bias) . w3 -> per-(row, warp-slice) partial
        float dot[8];
#pragma unroll
        for (int j = 0; j < 8; j++) dot[j] = 0.f;
#pragma unroll
        for (int mi = 0; mi < 4; mi++)
#pragma unroll
            for (int ni = 0; ni < 8; ni++) {
                int n = bn + wn + ni * 8 + ncol;
                float b0 = bias[n], b1 = bias[n + 1];
                float w0 = w3[n], w1 = w3[n + 1];
#pragma unroll
                for (int hf = 0; hf < 2; hf++) {
                    float vx = fmaxf(acc[mi][ni][hf * 2 + 0] + b0, 0.f);
                    float vy = fmaxf(acc[mi][ni][hf * 2 + 1] + b1, 0.f);
                    dot[mi * 2 + hf] += vx * w0 + vy * w1;
                }
            }
#pragma unroll
        for (int o = 1; o <= 2; o <<= 1)
#pragma unroll
            for (int j = 0; j < 8; j++)
                dot[j] += __shfl_xor_sync(0xffffffffu, dot[j], o);
        if ((lane & 3) == 0) {
            int g = blockIdx.x * 4 + (wn >> 6);
#pragma unroll
            for (int mi = 0; mi < 4; mi++)
#pragma unroll
                for (int hf = 0; hf < 2; hf++) {
                    int m = bm + wm + mi * 16 + mrow + hf * 8;
                    if (m < M) partials[(size_t)m * 16 + g] = dot[mi * 2 + hf];
                }
        }
        return;
    }

#pragma unroll
    for (int mi = 0; mi < 4; mi++) {
#pragma unroll
        for (int ni = 0; ni < 8; ni++) {
            int n0 = bn + wn + ni * 8 + ncol;
            float b0 = bias ? bias[n0] : 0.f;
            float b1 = bias ? bias[n0 + 1] : 0.f;
#pragma unroll
            for (int hf = 0; hf < 2; hf++) {
                int m = bm + wm + mi * 16 + mrow + hf * 8;
                if (m < M) {
                    float vx = acc[mi][ni][hf * 2 + 0] + b0;
                    float vy = acc[mi][ni][hf * 2 + 1] + b1;
                    if (relu) { vx = fmaxf(vx, 0.f); vy = fmaxf(vy, 0.f); }
                    if (C) *(float2*)(C + (size_t)m * ldc + n0) = make_float2(vx, vy);
                    else {
                        __half2 h = __floats2half2_rn(vx, vy);
                        float2 hfv = __half22float2(h);
                        __half2 l = __floats2half2_rn(vx - hfv.x, vy - hfv.y);
                        *(__half2*)(Ch + (size_t)m * ldc + n0) = h;
                        *(__half2*)(Cl + (size_t)m * ldc + n0) = l;
                    }
                }
            }
        }
    }
}

// ---------------- reduce16: out[i] = b[0] + sum_g partials[i][g] -------------
__global__ void reduce16(const float* __restrict__ partials, const float* __restrict__ b,
                         float* __restrict__ out, int M)
{
    int i = blockIdx.x * blockDim.x + threadIdx.x;
    if (i >= M) return;
    float s = b[0];
    const float4* p = (const float4*)(partials + (size_t)i * 16);
#pragma unroll
    for (int g = 0; g < 4; g++) {
        float4 v = p[g];
        s += v.x + v.y + v.z + v.w;
    }
    out[i] = s;
}

// ------------- transpose+split: W[k,1024] -> Hh/Hl [n,K] __half -------------
__global__ void transpose_split(const float* __restrict__ W,
                                __half* __restrict__ Hh, __half* __restrict__ Hl, int K)
{
    __shared__ float tile[32][33];
    int kx = blockIdx.x * 32, ny = blockIdx.y * 32;
    int tx = threadIdx.x, ty = threadIdx.y;   // 32 x 8
#pragma unroll
    for (int i = 0; i < 32; i += 8) {
        int k = kx + ty + i;
        if (k < K) tile[ty + i][tx] = W[(size_t)k * 1024 + ny + tx];
    }
    __syncthreads();
#pragma unroll
    for (int i = 0; i < 32; i += 8) {
        int n = ny + ty + i, k = kx + tx;
        if (k < K) {
            float v = tile[tx][ty + i];
            __half h = __float2half_rn(v);
            Hh[(size_t)n * K + k] = h;
            Hl[(size_t)n * K + k] = __float2half_rn(v - __half2float(h));
        }
    }
}

// ------------- split activations: X fp32 -> Xh, Xl fp16 -------------
__global__ void split_act(const float* __restrict__ X,
                          __half* __restrict__ Xh, __half* __restrict__ Xl, int n4)
{
    int i = blockIdx.x * blockDim.x + threadIdx.x;
    if (i >= n4) return;
    float4 v = ((const float4*)X)[i];
    __half2 h01 = __floats2half2_rn(v.x, v.y);
    __half2 h23 = __floats2half2_rn(v.z, v.w);
    float2 f01 = __half22float2(h01);
    float2 f23 = __half22float2(h23);
    __half2 l01 = __floats2half2_rn(v.x - f01.x, v.y - f01.y);
    __half2 l23 = __floats2half2_rn(v.z - f23.x, v.w - f23.y);
    ((__half2*)Xh)[i * 2] = h01; ((__half2*)Xh)[i * 2 + 1] = h23;
    ((__half2*)Xl)[i * 2] = l01; ((__half2*)Xl)[i * 2 + 1] = l23;
}

// ---------------- WB9[b] = width_embed[b] @ W1d + score_b1 ----------------
__global__ void wb9_kernel(const float* __restrict__ width_embed,
                           const float* __restrict__ W1, const float* __restrict__ b1)
{
    int bkt = blockIdx.x;
    int j4 = threadIdx.x;
    float4 acc = ((const float4*)b1)[j4];
#pragma unroll
    for (int k = 0; k < DD; k++) {
        float wv = width_embed[bkt * DD + k];
        float4 ww = ((const float4*)(W1 + (size_t)(2 * SD + ED + k) * HID))[j4];
        acc.x = fmaf(wv, ww.x, acc.x); acc.y = fmaf(wv, ww.y, acc.y);
        acc.z = fmaf(wv, ww.z, acc.z); acc.w = fmaf(wv, ww.w, acc.w);
    }
    ((float4*)(g_WB9 + (size_t)bkt * HID))[j4] = acc;
}

// ---------------- span kernel: g_i row (fp32) + h1 row (split fp16) -----------
__global__ void span_kernel(const float* __restrict__ states,
                            const float* __restrict__ embeds,
                            const float* __restrict__ width_embed,
                            const int* __restrict__ starts,
                            const int* __restrict__ widths,
                            float* __restrict__ gi,
                            __half* __restrict__ h1h, __half* __restrict__ h1l)
{
    const int n = blockIdx.x;
    const int s = starts[n];
    const int w = widths[n];
    const int e = s + w - 1;
    const int bucket = (w >= 1) + (w >= 2) + (w >= 3) + (w >= 4) +
                       (w >= 8) + (w >= 16) + (w >= 32) + (w >= 64);

    float wt[MAXW];
    float mx = -3.4e38f;
#pragma unroll
    for (int i = 0; i < MAXW; i++) {
        int p = s + i; if (p > T_TOK - 1) p = T_TOK - 1;
        float a = (i < w) ? g_attns[p] : -1e30f;
        wt[i] = a;
        mx = fmaxf(mx, a);
    }
    float sum = 0.f;
#pragma unroll
    for (int i = 0; i < MAXW; i++) {
        float v = (i < w) ? expf(wt[i] - mx) : 0.f;
        wt[i] = v; sum += v;
    }
    const float inv = 1.f / sum;

    const int tid = threadIdx.x;   // 256
    float* girow = gi + (size_t)n * GI;

    ((float4*)girow)[tid] = ((const float4*)(states + (size_t)s * SD))[tid];
    ((float4*)(girow + SD))[tid] = ((const float4*)(states + (size_t)e * SD))[tid];

    if (tid < 128) {
        float4 acc = make_float4(0.f, 0.f, 0.f, 0.f);
#pragma unroll
        for (int i = 0; i < MAXW; i++) {
            if (i < w) {
                float4 v = ((const float4*)(embeds + (size_t)(s + i) * ED))[tid];
                float ww = wt[i] * inv;
                acc.x = fmaf(ww, v.x, acc.x); acc.y = fmaf(ww, v.y, acc.y);
                acc.z = fmaf(ww, v.z, acc.z); acc.w = fmaf(ww, v.w, acc.w);
            }
        }
        ((float4*)(girow + 2 * SD))[tid] = acc;
    } else if (tid < 128 + DD) {
        int j = tid - 128;
        girow[2 * SD + ED + j] = width_embed[bucket * DD + j];
    }

    {
        float4 a = ((const float4*)(g_P12 + (size_t)s * 2048))[tid];
        float4 b = ((const float4*)(g_P12 + (size_t)e * 2048 + 1024))[tid];
        float4 c = ((const float4*)(g_WB9 + (size_t)bucket * HID))[tid];
        float4 acc = make_float4(a.x + b.x + c.x, a.y + b.y + c.y,
                                 a.z + b.z + c.z, a.w + b.w + c.w);
#pragma unroll
        for (int i = 0; i < MAXW; i++) {
            if (i < w) {
                float4 v = ((const float4*)(g_E1 + (size_t)(s + i) * HID))[tid];
                float ww = wt[i] * inv;
                acc.x = fmaf(ww, v.x, acc.x); acc.y = fmaf(ww, v.y, acc.y);
                acc.z = fmaf(ww, v.z, acc.z); acc.w = fmaf(ww, v.w, acc.w);
            }
        }
        acc.x = fmaxf(acc.x, 0.f); acc.y = fmaxf(acc.y, 0.f);
        acc.z = fmaxf(acc.z, 0.f); acc.w = fmaxf(acc.w, 0.f);
        __half2 h01 = __floats2half2_rn(acc.x, acc.y);
        __half2 h23 = __floats2half2_rn(acc.z, acc.w);
        float2 f01 = __half22float2(h01);
        float2 f23 = __half22float2(h23);
        __half2 l01 = __floats2half2_rn(acc.x - f01.x, acc.y - f01.y);
        __half2 l23 = __floats2half2_rn(acc.z - f23.x, acc.w - f23.y);
        ((__half2*)(h1h + (size_t)n * HID))[tid * 2] = h01;
        ((__half2*)(h1h + (size_t)n * HID))[tid * 2 + 1] = h23;
        ((__half2*)(h1l + (size_t)n * HID))[tid * 2] = l01;
        ((__half2*)(h1l + (size_t)n * HID))[tid * 2 + 1] = l23;
    }
}

// ---------------- launcher ----------------
extern "C" void kernel_launch(void* const* d_in, const int* in_sizes, int n_in,
                              void* d_out, int out_size)
{
    const float* states = (const float*)d_in[0];
    const float* embeds = (const float*)d_in[1];
    const float* aW1 = (const float*)d_in[2];
    const float* ab1 = (const float*)d_in[3];
    const float* aW2 = (const float*)d_in[4];
    const float* ab2 = (const float*)d_in[5];
    const float* aW3 = (const float*)d_in[6];
    const float* ab3 = (const float*)d_in[7];
    const float* sW1 = (const float*)d_in[8];
    const float* sb1 = (const float*)d_in[9];
    const float* sW2 = (const float*)d_in[10];
    const float* sb2 = (const float*)d_in[11];
    const float* sW3 = (const float*)d_in[12];
    const float* sb3 = (const float*)d_in[13];
    const float* wemb = (const float*)d_in[14];
    const int* starts = (const int*)d_in[15];
    const int* widths = (const int*)d_in[16];

    float* out = (float*)d_out;
    float* gi = out;
    float* scores = out + (size_t)NSPAN * GI;

    float *attns, *P12, *E1, *part;
    __half *A1h, *A1l, *h1h, *h1l, *Sth, *Stl, *Emh, *Eml;
    __half *Wa1h, *Wa1l, *Wa2h, *Wa2l, *Wp12h, *Wp12l, *We1h, *We1l, *Ws2h, *Ws2l;
    cudaGetSymbolAddress((void**)&attns, g_attns);
    cudaGetSymbolAddress((void**)&P12, g_P12);
    cudaGetSymbolAddress((void**)&E1, g_E1);
    cudaGetSymbolAddress((void**)&part, g_part);
    cudaGetSymbolAddress((void**)&A1h, g_A1h);
    cudaGetSymbolAddress((void**)&A1l, g_A1l);
    cudaGetSymbolAddress((void**)&h1h, g_h1h);
    cudaGetSymbolAddress((void**)&h1l, g_h1l);
    cudaGetSymbolAddress((void**)&Sth, g_Sth);
    cudaGetSymbolAddress((void**)&Stl, g_Stl);
    cudaGetSymbolAddress((void**)&Emh, g_Emh);
    cudaGetSymbolAddress((void**)&Eml, g_Eml);
    cudaGetSymbolAddress((void**)&Wa1h, g_Wa1h);
    cudaGetSymbolAddress((void**)&Wa1l, g_Wa1l);
    cudaGetSymbolAddress((void**)&Wa2h, g_Wa2h);
    cudaGetSymbolAddress((void**)&Wa2l, g_Wa2l);
    cudaGetSymbolAddress((void**)&Wp12h, g_Wp12h);
    cudaGetSymbolAddress((void**)&Wp12l, g_Wp12l);
    cudaGetSymbolAddress((void**)&We1h, g_We1h);
    cudaGetSymbolAddress((void**)&We1l, g_We1l);
    cudaGetSymbolAddress((void**)&Ws2h, g_Ws2h);
    cudaGetSymbolAddress((void**)&Ws2l, g_Ws2l);

    cudaFuncSetAttribute(hgemm_x3, cudaFuncAttributeMaxDynamicSharedMemorySize, GEMM_SMEM);

    dim3 tb(32, 8);
    // 1-3: prerequisites for GEMM #4
    split_act<<<(T_TOK * SD / 4 + 255) / 256, 256>>>(states, Sth, Stl, T_TOK * SD / 4);
    split_act<<<(T_TOK * ED / 4 + 255) / 256, 256>>>(embeds, Emh, Eml, T_TOK * ED / 4);
    transpose_split<<<dim3(32, 32), tb>>>(aW1, Wa1h, Wa1l, SD);

    dim3 gT(1024 / TN, T_TOK / TM);   // 4 x 32
    // #4: attn layer1 -> A1 split
    hgemm_x3<<<gT, 256, GEMM_SMEM>>>(Sth, Stl, Wa1h, Wa1l, ab1,
                                     nullptr, A1h, A1l, nullptr, nullptr,
                                     T_TOK, SD, HID, 1);
    // #5
    transpose_split<<<dim3(32, 32), tb>>>(aW2, Wa2h, Wa2l, HID);
    // #6: attn layer2 fused with layer3 dot -> partials
    hgemm_x3<<<gT, 256, GEMM_SMEM>>>(A1h, A1l, Wa2h, Wa2l, ab2,
                                     nullptr, nullptr, nullptr, aW3, part,
                                     T_TOK, HID, 0, 1);
    reduce16<<<(T_TOK + 255) / 256, 256>>>(part, ab3, attns, T_TOK);

    // weight prep for score path
    transpose_split<<<dim3(32, 32), tb>>>(sW1, Wp12h, Wp12l, SD);
    transpose_split<<<dim3(32, 32), tb>>>(sW1 + (size_t)SD * HID,
                                          Wp12h + (size_t)1024 * SD, Wp12l + (size_t)1024 * SD, SD);
    transpose_split<<<dim3(16, 32), tb>>>(sW1 + (size_t)2 * SD * HID, We1h, We1l, ED);
    transpose_split<<<dim3(32, 32), tb>>>(sW2, Ws2h, Ws2l, HID);
    wb9_kernel<<<9, 256>>>(wemb, sW1, sb1);

    // P12 = states @ [W1a|W1b] (N=2048), E1 = embeds @ W1c
    dim3 gP(2048 / TN, T_TOK / TM);   // 8 x 32
    hgemm_x3<<<gP, 256, GEMM_SMEM>>>(Sth, Stl, Wp12h, Wp12l, nullptr,
                                     P12, nullptr, nullptr, nullptr, nullptr,
                                     T_TOK, SD, 2048, 0);
    hgemm_x3<<<gT, 256, GEMM_SMEM>>>(Emh, Eml, We1h, We1l, nullptr,
                                     E1, nullptr, nullptr, nullptr, nullptr,
                                     T_TOK, ED, HID, 0);

    // per-span: g_i output + fused layer-1 (h1 split)
    span_kernel<<<NSPAN, 256>>>(states, embeds, wemb, starts, widths, gi, h1h, h1l);

    // score layer-2 fused with layer-3 dot -> partials -> scores
    dim3 gN(1024 / TN, (NSPAN + TM - 1) / TM);   // 4 x 320
    hgemm_x3<<<gN, 256, GEMM_SMEM>>>(h1h, h1l, Ws2h, Ws2l, sb2,
                                     nullptr, nullptr, nullptr, sW3, part,
                                     NSPAN, HID, 0, 1);
    reduce16<<<(NSPAN + 255) / 256, 256>>>(part, sb3, scores, NSPAN);
}

// round 9
// speedup vs baseline: 2.3870x; 1.0922x over previous
#include <cuda_runtime.h>
#include <cuda_fp16.h>
#include <cstdint>

#define T_TOK 4096
#define SD    1024
#define ED    512
#define DD    20
#define HID   1024
#define GI    2580
#define NSPAN 40915
#define MAXW  10

// ---------------- scratch (static device globals; no allocations) ----------------
__device__ __half g_A1h[(size_t)T_TOK * HID];
__device__ __half g_A1l[(size_t)T_TOK * HID];
__device__ float  g_attns[T_TOK];
__device__ float  g_P12[(size_t)T_TOK * 2048];
__device__ float  g_E1[(size_t)T_TOK * HID];
__device__ float  g_WB9[9 * HID];
__device__ __half g_h1h[(size_t)NSPAN * HID];
__device__ __half g_h1l[(size_t)NSPAN * HID];
__device__ float  g_part[(size_t)NSPAN * 32];
// split activations
__device__ __half g_Sth[(size_t)T_TOK * SD];
__device__ __half g_Stl[(size_t)T_TOK * SD];
__device__ __half g_Emh[(size_t)T_TOK * ED];
__device__ __half g_Eml[(size_t)T_TOK * ED];
// transposed+split weights [N rows, K cols], hi/lo __half
__device__ __half g_Wa1h[(size_t)HID * SD], g_Wa1l[(size_t)HID * SD];
__device__ __half g_Wa2h[(size_t)HID * HID], g_Wa2l[(size_t)HID * HID];
__device__ __half g_Wp12h[(size_t)2048 * SD], g_Wp12l[(size_t)2048 * SD];
__device__ __half g_We1h[(size_t)HID * ED], g_We1l[(size_t)HID * ED];
__device__ __half g_Ws2h[(size_t)HID * HID], g_Ws2l[(size_t)HID * HID];

// ======================= helpers =======================
__device__ __forceinline__ uint32_t smem_u32(const void* p) {
    uint32_t a;
    asm("{ .reg .u64 t; cvta.to.shared.u64 t, %1; cvt.u32.u64 %0, t; }" : "=r"(a) : "l"(p));
    return a;
}
__device__ __forceinline__ void ldmx4(uint32_t* r, uint32_t addr) {
    asm volatile("ldmatrix.sync.aligned.m8n8.x4.shared.b16 {%0,%1,%2,%3}, [%4];"
                 : "=r"(r[0]), "=r"(r[1]), "=r"(r[2]), "=r"(r[3]) : "r"(addr));
}
__device__ __forceinline__ void mma16816(float* c, const uint32_t* a, const uint32_t* b) {
    asm volatile(
        "mma.sync.aligned.m16n8k16.row.col.f32.f16.f16.f32 "
        "{%0,%1,%2,%3}, {%4,%5,%6,%7}, {%8,%9}, {%0,%1,%2,%3};"
        : "+f"(c[0]), "+f"(c[1]), "+f"(c[2]), "+f"(c[3])
        : "r"(a[0]), "r"(a[1]), "r"(a[2]), "r"(a[3]), "r"(b[0]), "r"(b[1]));
}
__device__ __forceinline__ void cp16(uint32_t dst, const void* src, bool ok) {
    int sz = ok ? 16 : 0;
    asm volatile("cp.async.ca.shared.global [%0], [%1], 16, %2;" :: "r"(dst), "l"(src), "r"(sz));
}
#define CP_COMMIT() asm volatile("cp.async.commit_group;" ::: "memory")
#define CP_WAIT(n)  asm volatile("cp.async.wait_group %0;" :: "n"(n) : "memory")

// ======================= fp16x3 mma.sync GEMM, cp.async 2-stage =============
// C[M,N] = A @ B^T with A,B pre-split into fp16 hi/lo ([rows,K] K-major).
// CTA tile 128x128, warp tile 64x32, KC=32, 2 CTAs/SM. Dekker hh+hl+lh.
#define TM 128
#define TN 128
#define KC 32
#define RS 80
#define A_B (TM * RS)               // 10240
#define B_B (TN * RS)               // 10240
#define STAGE_B (2 * A_B + 2 * B_B) // 40960
#define STAGES 2
#define GEMM_SMEM (STAGES * STAGE_B)  // 81920

__global__ __launch_bounds__(256, 2) void hgemm_x3(
    const __half* __restrict__ Ah, const __half* __restrict__ Al,
    const __half* __restrict__ Bh, const __half* __restrict__ Bl,
    const float* __restrict__ bias,
    float* __restrict__ C, __half* __restrict__ Ch, __half* __restrict__ Cl,
    const float* __restrict__ w3, float* __restrict__ partials,
    int M, int K, int ldc, int relu)
{
    extern __shared__ char smem[];
    const uint32_t sbase = smem_u32(smem);

    const int tid = threadIdx.x;
    const int lane = tid & 31;
    const int wid = tid >> 5;
    const int wm = (wid >> 2) * 64;
    const int wn = (wid & 3) * 32;
    const int bn = blockIdx.x * TN;     // N fastest -> A tile L2 reuse
    const int bm = blockIdx.y * TM;

    // cp.async plan: A and B each 512 16B-units, 2/thread
    uint32_t soffs[2]; size_t agoff[2], bgoff[2]; bool aok[2];
#pragma unroll
    for (int i = 0; i < 2; i++) {
        int u = tid + 256 * i;
        int row = u >> 2, seg = u & 3;
        soffs[i] = (uint32_t)(row * RS + seg * 16);
        int ar = bm + row; aok[i] = ar < M; if (ar > M - 1) ar = M - 1;
        agoff[i] = (size_t)ar * K + seg * 8;
        bgoff[i] = (size_t)(bn + row) * K + seg * 8;
    }

    const int nchunks = K / KC;

    // prologue: stage 0
    {
        uint32_t sb = sbase;
#pragma unroll
        for (int i = 0; i < 2; i++) {
            cp16(sb + soffs[i],             Ah + agoff[i], aok[i]);
            cp16(sb + A_B + soffs[i],       Al + agoff[i], aok[i]);
            cp16(sb + 2 * A_B + soffs[i],       Bh + bgoff[i], true);
            cp16(sb + 2 * A_B + B_B + soffs[i], Bl + bgoff[i], true);
        }
        CP_COMMIT();
    }

    float acc[4][4][4];
#pragma unroll
    for (int mi = 0; mi < 4; mi++)
#pragma unroll
        for (int ni = 0; ni < 4; ni++)
#pragma unroll
            for (int q = 0; q < 4; q++) acc[mi][ni][q] = 0.f;

    const int lr = lane & 15;
    const int ch = (lane >> 4) * 16;

    for (int c = 0; c < nchunks; ++c) {
        CP_WAIT(0);
        __syncthreads();

        // issue next chunk into the other stage
        if (c + 1 < nchunks) {
            uint32_t sb = sbase + ((c + 1) & 1) * STAGE_B;
            int kc = (c + 1) * KC;
#pragma unroll
            for (int i = 0; i < 2; i++) {
                cp16(sb + soffs[i],             Ah + agoff[i] + kc, aok[i]);
                cp16(sb + A_B + soffs[i],       Al + agoff[i] + kc, aok[i]);
                cp16(sb + 2 * A_B + soffs[i],       Bh + bgoff[i] + kc, true);
                cp16(sb + 2 * A_B + B_B + soffs[i], Bl + bgoff[i] + kc, true);
            }
        }
        CP_COMMIT();

        const uint32_t sb = sbase + (c & 1) * STAGE_B;
#pragma unroll
        for (int ks = 0; ks < 2; ks++) {
            const uint32_t colb = (uint32_t)(ks * 32 + ch);
            uint32_t aH[4][4], aL[4][4], bH[4][2], bL[4][2];
            // phase 1: A-hi, B-hi -> hh
#pragma unroll
            for (int mi = 0; mi < 4; mi++) {
                uint32_t rowo = (uint32_t)((wm + mi * 16 + lr) * RS) + colb;
                ldmx4(aH[mi], sb + rowo);
            }
#pragma unroll
            for (int g = 0; g < 2; g++) {
                uint32_t rowo = (uint32_t)((wn + g * 16 + lr) * RS) + colb;
                uint32_t r[4];
                ldmx4(r, sb + 2 * A_B + rowo);
                bH[g * 2][0] = r[0]; bH[g * 2][1] = r[2];
                bH[g * 2 + 1][0] = r[1]; bH[g * 2 + 1][1] = r[3];
            }
#pragma unroll
            for (int mi = 0; mi < 4; mi++)
#pragma unroll
                for (int ni = 0; ni < 4; ni++)
                    mma16816(acc[mi][ni], aH[mi], bH[ni]);
            // phase 2: B-lo -> hl
#pragma unroll
            for (int g = 0; g < 2; g++) {
                uint32_t rowo = (uint32_t)((wn + g * 16 + lr) * RS) + colb;
                uint32_t r[4];
                ldmx4(r, sb + 2 * A_B + B_B + rowo);
                bL[g * 2][0] = r[0]; bL[g * 2][1] = r[2];
                bL[g * 2 + 1][0] = r[1]; bL[g * 2 + 1][1] = r[3];
            }
#pragma unroll
            for (int mi = 0; mi < 4; mi++)
#pragma unroll
                for (int ni = 0; ni < 4; ni++)
                    mma16816(acc[mi][ni], aH[mi], bL[ni]);
            // phase 3: A-lo -> lh
#pragma unroll
            for (int mi = 0; mi < 4; mi++) {
                uint32_t rowo = (uint32_t)((wm + mi * 16 + lr) * RS) + colb;
                ldmx4(aL[mi], sb + A_B + rowo);
            }
#pragma unroll
            for (int mi = 0; mi < 4; mi++)
#pragma unroll
                for (int ni = 0; ni < 4; ni++)
                    mma16816(acc[mi][ni], aL[mi], bH[ni]);
        }
    }

    // ---------------- epilogue ----------------
    const int mrow = lane >> 2;
    const int ncol = (lane & 3) * 2;

    if (partials) {
        float dot[8];
#pragma unroll
        for (int j = 0; j < 8; j++) dot[j] = 0.f;
#pragma unroll
        for (int mi = 0; mi < 4; mi++)
#pragma unroll
            for (int ni = 0; ni < 4; ni++) {
                int n = bn + wn + ni * 8 + ncol;
                float b0 = bias[n], b1 = bias[n + 1];
                float w0 = w3[n], w1 = w3[n + 1];
#pragma unroll
                for (int hf = 0; hf < 2; hf++) {
                    float vx = fmaxf(acc[mi][ni][hf * 2 + 0] + b0, 0.f);
                    float vy = fmaxf(acc[mi][ni][hf * 2 + 1] + b1, 0.f);
                    dot[mi * 2 + hf] += vx * w0 + vy * w1;
                }
            }
#pragma unroll
        for (int o = 1; o <= 2; o <<= 1)
#pragma unroll
            for (int j = 0; j < 8; j++)
                dot[j] += __shfl_xor_sync(0xffffffffu, dot[j], o);
        if ((lane & 3) == 0) {
            int g = blockIdx.x * 4 + (wn >> 5);
#pragma unroll
            for (int mi = 0; mi < 4; mi++)
#pragma unroll
                for (int hf = 0; hf < 2; hf++) {
                    int m = bm + wm + mi * 16 + mrow + hf * 8;
                    if (m < M) partials[(size_t)m * 32 + g] = dot[mi * 2 + hf];
                }
        }
        return;
    }

#pragma unroll
    for (int mi = 0; mi < 4; mi++) {
#pragma unroll
        for (int ni = 0; ni < 4; ni++) {
            int n0 = bn + wn + ni * 8 + ncol;
            float b0 = bias ? bias[n0] : 0.f;
            float b1 = bias ? bias[n0 + 1] : 0.f;
#pragma unroll
            for (int hf = 0; hf < 2; hf++) {
                int m = bm + wm + mi * 16 + mrow + hf * 8;
                if (m < M) {
                    float vx = acc[mi][ni][hf * 2 + 0] + b0;
                    float vy = acc[mi][ni][hf * 2 + 1] + b1;
                    if (relu) { vx = fmaxf(vx, 0.f); vy = fmaxf(vy, 0.f); }
                    if (C) *(float2*)(C + (size_t)m * ldc + n0) = make_float2(vx, vy);
                    else {
                        __half2 h = __floats2half2_rn(vx, vy);
                        float2 hfv = __half22float2(h);
                        __half2 l = __floats2half2_rn(vx - hfv.x, vy - hfv.y);
                        *(__half2*)(Ch + (size_t)m * ldc + n0) = h;
                        *(__half2*)(Cl + (size_t)m * ldc + n0) = l;
                    }
                }
            }
        }
    }
}

// ---------------- reduce32: out[i] = b[0] + sum_g partials[i][g] -------------
__global__ void reduce32(const float* __restrict__ partials, const float* __restrict__ b,
                         float* __restrict__ out, int M)
{
    int i = blockIdx.x * blockDim.x + threadIdx.x;
    if (i >= M) return;
    float s = b[0];
    const float4* p = (const float4*)(partials + (size_t)i * 32);
#pragma unroll
    for (int g = 0; g < 8; g++) {
        float4 v = p[g];
        s += v.x + v.y + v.z + v.w;
    }
    out[i] = s;
}

// ------------- transpose+split: W[k,1024] -> Hh/Hl [n,K] __half -------------
__global__ void transpose_split(const float* __restrict__ W,
                                __half* __restrict__ Hh, __half* __restrict__ Hl, int K)
{
    __shared__ float tile[32][33];
    int kx = blockIdx.x * 32, ny = blockIdx.y * 32;
    int tx = threadIdx.x, ty = threadIdx.y;   // 32 x 8
#pragma unroll
    for (int i = 0; i < 32; i += 8) {
        int k = kx + ty + i;
        if (k < K) tile[ty + i][tx] = W[(size_t)k * 1024 + ny + tx];
    }
    __syncthreads();
#pragma unroll
    for (int i = 0; i < 32; i += 8) {
        int n = ny + ty + i, k = kx + tx;
        if (k < K) {
            float v = tile[tx][ty + i];
            __half h = __float2half_rn(v);
            Hh[(size_t)n * K + k] = h;
            Hl[(size_t)n * K + k] = __float2half_rn(v - __half2float(h));
        }
    }
}

// ------------- split activations: X fp32 -> Xh, Xl fp16 -------------
__global__ void split_act(const float* __restrict__ X,
                          __half* __restrict__ Xh, __half* __restrict__ Xl, int n4)
{
    int i = blockIdx.x * blockDim.x + threadIdx.x;
    if (i >= n4) return;
    float4 v = ((const float4*)X)[i];
    __half2 h01 = __floats2half2_rn(v.x, v.y);
    __half2 h23 = __floats2half2_rn(v.z, v.w);
    float2 f01 = __half22float2(h01);
    float2 f23 = __half22float2(h23);
    __half2 l01 = __floats2half2_rn(v.x - f01.x, v.y - f01.y);
    __half2 l23 = __floats2half2_rn(v.z - f23.x, v.w - f23.y);
    ((__half2*)Xh)[i * 2] = h01; ((__half2*)Xh)[i * 2 + 1] = h23;
    ((__half2*)Xl)[i * 2] = l01; ((__half2*)Xl)[i * 2 + 1] = l23;
}

// ---------------- WB9[b] = width_embed[b] @ W1d + score_b1 ----------------
__global__ void wb9_kernel(const float* __restrict__ width_embed,
                           const float* __restrict__ W1, const float* __restrict__ b1)
{
    int bkt = blockIdx.x;
    int j4 = threadIdx.x;
    float4 acc = ((const float4*)b1)[j4];
#pragma unroll
    for (int k = 0; k < DD; k++) {
        float wv = width_embed[bkt * DD + k];
        float4 ww = ((const float4*)(W1 + (size_t)(2 * SD + ED + k) * HID))[j4];
        acc.x = fmaf(wv, ww.x, acc.x); acc.y = fmaf(wv, ww.y, acc.y);
        acc.z = fmaf(wv, ww.z, acc.z); acc.w = fmaf(wv, ww.w, acc.w);
    }
    ((float4*)(g_WB9 + (size_t)bkt * HID))[j4] = acc;
}

// ---------------- span kernel: g_i row (fp32) + h1 row (split fp16) -----------
__global__ void span_kernel(const float* __restrict__ states,
                            const float* __restrict__ embeds,
                            const float* __restrict__ width_embed,
                            const int* __restrict__ starts,
                            const int* __restrict__ widths,
                            float* __restrict__ gi,
                            __half* __restrict__ h1h, __half* __restrict__ h1l)
{
    const int n = blockIdx.x;
    const int s = starts[n];
    const int w = widths[n];
    const int e = s + w - 1;
    const int bucket = (w >= 1) + (w >= 2) + (w >= 3) + (w >= 4) +
                       (w >= 8) + (w >= 16) + (w >= 32) + (w >= 64);

    float wt[MAXW];
    float mx = -3.4e38f;
#pragma unroll
    for (int i = 0; i < MAXW; i++) {
        int p = s + i; if (p > T_TOK - 1) p = T_TOK - 1;
        float a = (i < w) ? g_attns[p] : -1e30f;
        wt[i] = a;
        mx = fmaxf(mx, a);
    }
    float sum = 0.f;
#pragma unroll
    for (int i = 0; i < MAXW; i++) {
        float v = (i < w) ? expf(wt[i] - mx) : 0.f;
        wt[i] = v; sum += v;
    }
    const float inv = 1.f / sum;

    const int tid = threadIdx.x;   // 256
    float* girow = gi + (size_t)n * GI;

    ((float4*)girow)[tid] = ((const float4*)(states + (size_t)s * SD))[tid];
    ((float4*)(girow + SD))[tid] = ((const float4*)(states + (size_t)e * SD))[tid];

    if (tid < 128) {
        float4 acc = make_float4(0.f, 0.f, 0.f, 0.f);
#pragma unroll
        for (int i = 0; i < MAXW; i++) {
            if (i < w) {
                float4 v = ((const float4*)(embeds + (size_t)(s + i) * ED))[tid];
                float ww = wt[i] * inv;
                acc.x = fmaf(ww, v.x, acc.x); acc.y = fmaf(ww, v.y, acc.y);
                acc.z = fmaf(ww, v.z, acc.z); acc.w = fmaf(ww, v.w, acc.w);
            }
        }
        ((float4*)(girow + 2 * SD))[tid] = acc;
    } else if (tid < 128 + DD) {
        int j = tid - 128;
        girow[2 * SD + ED + j] = width_embed[bucket * DD + j];
    }

    {
        float4 a = ((const float4*)(g_P12 + (size_t)s * 2048))[tid];
        float4 b = ((const float4*)(g_P12 + (size_t)e * 2048 + 1024))[tid];
        float4 c = ((const float4*)(g_WB9 + (size_t)bucket * HID))[tid];
        float4 acc = make_float4(a.x + b.x + c.x, a.y + b.y + c.y,
                                 a.z + b.z + c.z, a.w + b.w + c.w);
#pragma unroll
        for (int i = 0; i < MAXW; i++) {
            if (i < w) {
                float4 v = ((const float4*)(g_E1 + (size_t)(s + i) * HID))[tid];
                float ww = wt[i] * inv;
                acc.x = fmaf(ww, v.x, acc.x); acc.y = fmaf(ww, v.y, acc.y);
                acc.z = fmaf(ww, v.z, acc.z); acc.w = fmaf(ww, v.w, acc.w);
            }
        }
        acc.x = fmaxf(acc.x, 0.f); acc.y = fmaxf(acc.y, 0.f);
        acc.z = fmaxf(acc.z, 0.f); acc.w = fmaxf(acc.w, 0.f);
        __half2 h01 = __floats2half2_rn(acc.x, acc.y);
        __half2 h23 = __floats2half2_rn(acc.z, acc.w);
        float2 f01 = __half22float2(h01);
        float2 f23 = __half22float2(h23);
        __half2 l01 = __floats2half2_rn(acc.x - f01.x, acc.y - f01.y);
        __half2 l23 = __floats2half2_rn(acc.z - f23.x, acc.w - f23.y);
        ((__half2*)(h1h + (size_t)n * HID))[tid * 2] = h01;
        ((__half2*)(h1h + (size_t)n * HID))[tid * 2 + 1] = h23;
        ((__half2*)(h1l + (size_t)n * HID))[tid * 2] = l01;
        ((__half2*)(h1l + (size_t)n * HID))[tid * 2 + 1] = l23;
    }
}

// ---------------- launcher ----------------
extern "C" void kernel_launch(void* const* d_in, const int* in_sizes, int n_in,
                              void* d_out, int out_size)
{
    const float* states = (const float*)d_in[0];
    const float* embeds = (const float*)d_in[1];
    const float* aW1 = (const float*)d_in[2];
    const float* ab1 = (const float*)d_in[3];
    const float* aW2 = (const float*)d_in[4];
    const float* ab2 = (const float*)d_in[5];
    const float* aW3 = (const float*)d_in[6];
    const float* ab3 = (const float*)d_in[7];
    const float* sW1 = (const float*)d_in[8];
    const float* sb1 = (const float*)d_in[9];
    const float* sW2 = (const float*)d_in[10];
    const float* sb2 = (const float*)d_in[11];
    const float* sW3 = (const float*)d_in[12];
    const float* sb3 = (const float*)d_in[13];
    const float* wemb = (const float*)d_in[14];
    const int* starts = (const int*)d_in[15];
    const int* widths = (const int*)d_in[16];

    float* out = (float*)d_out;
    float* gi = out;
    float* scores = out + (size_t)NSPAN * GI;

    float *attns, *P12, *E1, *part;
    __half *A1h, *A1l, *h1h, *h1l, *Sth, *Stl, *Emh, *Eml;
    __half *Wa1h, *Wa1l, *Wa2h, *Wa2l, *Wp12h, *Wp12l, *We1h, *We1l, *Ws2h, *Ws2l;
    cudaGetSymbolAddress((void**)&attns, g_attns);
    cudaGetSymbolAddress((void**)&P12, g_P12);
    cudaGetSymbolAddress((void**)&E1, g_E1);
    cudaGetSymbolAddress((void**)&part, g_part);
    cudaGetSymbolAddress((void**)&A1h, g_A1h);
    cudaGetSymbolAddress((void**)&A1l, g_A1l);
    cudaGetSymbolAddress((void**)&h1h, g_h1h);
    cudaGetSymbolAddress((void**)&h1l, g_h1l);
    cudaGetSymbolAddress((void**)&Sth, g_Sth);
    cudaGetSymbolAddress((void**)&Stl, g_Stl);
    cudaGetSymbolAddress((void**)&Emh, g_Emh);
    cudaGetSymbolAddress((void**)&Eml, g_Eml);
    cudaGetSymbolAddress((void**)&Wa1h, g_Wa1h);
    cudaGetSymbolAddress((void**)&Wa1l, g_Wa1l);
    cudaGetSymbolAddress((void**)&Wa2h, g_Wa2h);
    cudaGetSymbolAddress((void**)&Wa2l, g_Wa2l);
    cudaGetSymbolAddress((void**)&Wp12h, g_Wp12h);
    cudaGetSymbolAddress((void**)&Wp12l, g_Wp12l);
    cudaGetSymbolAddress((void**)&We1h, g_We1h);
    cudaGetSymbolAddress((void**)&We1l, g_We1l);
    cudaGetSymbolAddress((void**)&Ws2h, g_Ws2h);
    cudaGetSymbolAddress((void**)&Ws2l, g_Ws2l);

    cudaFuncSetAttribute(hgemm_x3, cudaFuncAttributeMaxDynamicSharedMemorySize, GEMM_SMEM);

    dim3 tb(32, 8);
    // 1-3: prerequisites for GEMM #4
    split_act<<<(T_TOK * SD / 4 + 255) / 256, 256>>>(states, Sth, Stl, T_TOK * SD / 4);
    split_act<<<(T_TOK * ED / 4 + 255) / 256, 256>>>(embeds, Emh, Eml, T_TOK * ED / 4);
    transpose_split<<<dim3(32, 32), tb>>>(aW1, Wa1h, Wa1l, SD);

    dim3 gT(1024 / TN, T_TOK / TM);   // 8 x 32
    // #4: attn layer1 -> A1 split
    hgemm_x3<<<gT, 256, GEMM_SMEM>>>(Sth, Stl, Wa1h, Wa1l, ab1,
                                     nullptr, A1h, A1l, nullptr, nullptr,
                                     T_TOK, SD, HID, 1);
    // #5
    transpose_split<<<dim3(32, 32), tb>>>(aW2, Wa2h, Wa2l, HID);
    // #6: attn layer2 fused with layer3 dot -> partials
    hgemm_x3<<<gT, 256, GEMM_SMEM>>>(A1h, A1l, Wa2h, Wa2l, ab2,
                                     nullptr, nullptr, nullptr, aW3, part,
                                     T_TOK, HID, 0, 1);
    reduce32<<<(T_TOK + 255) / 256, 256>>>(part, ab3, attns, T_TOK);

    // weight prep for score path
    transpose_split<<<dim3(32, 32), tb>>>(sW1, Wp12h, Wp12l, SD);
    transpose_split<<<dim3(32, 32), tb>>>(sW1 + (size_t)SD * HID,
                                          Wp12h + (size_t)1024 * SD, Wp12l + (size_t)1024 * SD, SD);
    transpose_split<<<dim3(16, 32), tb>>>(sW1 + (size_t)2 * SD * HID, We1h, We1l, ED);
    transpose_split<<<dim3(32, 32), tb>>>(sW2, Ws2h, Ws2l, HID);
    wb9_kernel<<<9, 256>>>(wemb, sW1, sb1);

    // P12 = states @ [W1a|W1b] (N=2048), E1 = embeds @ W1c
    dim3 gP(2048 / TN, T_TOK / TM);   // 16 x 32
    hgemm_x3<<<gP, 256, GEMM_SMEM>>>(Sth, Stl, Wp12h, Wp12l, nullptr,
                                     P12, nullptr, nullptr, nullptr, nullptr,
                                     T_TOK, SD, 2048, 0);
    hgemm_x3<<<gT, 256, GEMM_SMEM>>>(Emh, Eml, We1h, We1l, nullptr,
                                     E1, nullptr, nullptr, nullptr, nullptr,
                                     T_TOK, ED, HID, 0);

    // per-span: g_i output + fused layer-1 (h1 split)
    span_kernel<<<NSPAN, 256>>>(states, embeds, wemb, starts, widths, gi, h1h, h1l);

    // score layer-2 fused with layer-3 dot -> partials -> scores
    dim3 gN(1024 / TN, (NSPAN + TM - 1) / TM);   // 8 x 320
    hgemm_x3<<<gN, 256, GEMM_SMEM>>>(h1h, h1l, Ws2h, Ws2l, sb2,
                                     nullptr, nullptr, nullptr, sW3, part,
                                     NSPAN, HID, 0, 1);
    reduce32<<<(NSPAN + 255) / 256, 256>>>(part, sb3, scores, NSPAN);
}